// round 13
// baseline (speedup 1.0000x reference)
#include <cuda_runtime.h>
#include <cuda_fp16.h>
#include <stdint.h>
#include <math.h>

typedef __half fp16;

#define NIMG 448
#define TAPSZ 16384
#define ZSZ   4864
#define AHI   4864
#define LASZ  23040
#define LBOFF (AHI + 2*LASZ)           // 50944
#define LSMEM (LBOFF + 9*18432)        // 216832
#define CASZ  41472
#define CBOFF (AHI + CASZ)             // 46336
#define CSMEM (CBOFF + 4*18432)        // 120064

__device__ fp16  g_xeh[(size_t)NIMG*256*64];
__device__ float g_xz[(size_t)2*NIMG*2*32768];   // [dir][img][ncol][n4(32)][px(256)][4]
__device__ fp16  g_q0h[(size_t)NIMG*256*64], g_q0l[(size_t)NIMG*256*64];  // dir0 seq
__device__ fp16  g_q1h[(size_t)NIMG*256*64], g_q1l[(size_t)NIMG*256*64];  // dir1 seq
__device__ float g_cst[524288];
__device__ fp16  g_w[(size_t)90*TAPSZ];
__device__ fp16  g_zeroh[16384];
__device__ unsigned g_grpbar[1024];              // 32 counters, 128B apart

__device__ __forceinline__ uint32_t smem_u32(const void* p) {
    uint32_t a;
    asm("{ .reg .u64 t; cvta.to.shared.u64 t, %1; cvt.u32.u64 %0, t; }" : "=r"(a) : "l"(p));
    return a;
}
__device__ __forceinline__ void ldsm4(uint32_t* r, uint32_t addr) {
    asm volatile("ldmatrix.sync.aligned.m8n8.x4.shared.b16 {%0,%1,%2,%3}, [%4];"
        : "=r"(r[0]), "=r"(r[1]), "=r"(r[2]), "=r"(r[3]) : "r"(addr));
}
__device__ __forceinline__ void mma16816(float* c, const uint32_t* a, const uint32_t* b) {
    asm volatile("mma.sync.aligned.m16n8k16.row.col.f32.f16.f16.f32 "
        "{%0,%1,%2,%3}, {%4,%5,%6,%7}, {%8,%9}, {%0,%1,%2,%3};"
        : "+f"(c[0]), "+f"(c[1]), "+f"(c[2]), "+f"(c[3])
        : "r"(a[0]), "r"(a[1]), "r"(a[2]), "r"(a[3]), "r"(b[0]), "r"(b[1]));
}
__device__ __forceinline__ void cpa16(uint32_t dst, const void* src) {
    asm volatile("cp.async.cg.shared.global [%0], [%1], 16;" :: "r"(dst), "l"(src) : "memory");
}
__device__ __forceinline__ void cp_commit() { asm volatile("cp.async.commit_group;" ::: "memory"); }
__device__ __forceinline__ void cp_wait2()  { asm volatile("cp.async.wait_group 2;" ::: "memory"); }
__device__ __forceinline__ void cp_wait1()  { asm volatile("cp.async.wait_group 1;" ::: "memory"); }
__device__ __forceinline__ void cp_wait0()  { asm volatile("cp.async.wait_group 0;" ::: "memory"); }
__device__ __forceinline__ float sigm(float x) { return __fdividef(1.f, 1.f + __expf(-x)); }

template<int TERMS>
__device__ __forceinline__ void fill_A(char* sm, uint32_t asz,
        const fp16* hsrc, const fp16* lsrc, int r0, int nrows, int tid) {
    const uint4* hv = (const uint4*)hsrc;
    const uint4* lv = (const uint4*)lsrc;
    const uint4 z = make_uint4(0, 0, 0, 0);
    int tot = nrows * 16 * 8;
    for (int i = tid; i < tot; i += 256) {
        int ch = i & 7, p = i >> 3;
        int hr = p >> 4, c = p & 15;
        int row = r0 - 1 + hr;
        bool v = (row >= 0 && row < 16);
        int gi = (row * 16 + c) * 8 + ch;
        uint4 hval = v ? hv[gi] : z;
        *(uint4*)(sm + AHI + p * 144 + ch * 16) = hval;
        if (TERMS == 2) {
            uint4 lval = v ? lv[gi] : z;
            *(uint4*)(sm + AHI + asz + p * 144 + ch * 16) = lval;
        }
    }
}

__device__ __forceinline__ void prefB(char* sm, uint32_t boff, int slot,
        const fp16* w, int tap, int ncol, int tid) {
    char* dh = sm + boff + slot * 18432;
    const char* g = (const char*)w + (size_t)tap * 32768 + (size_t)ncol * 16384;
    #pragma unroll
    for (int jj = 0; jj < 4; jj++) {
        int j = tid * 4 + jj;
        int row = j >> 3, of = (j & 7) * 16;
        cpa16(smem_u32(dh + row * 144 + of), g + row * 128 + of);
    }
    cp_commit();
}

__device__ __forceinline__ void prefB_all(char* sm, const fp16* w, int ncol, int tid) {
    const char* g = (const char*)w + (size_t)ncol * 16384;
    for (int i = tid; i < 9216; i += 256) {
        int tap = i >> 10, j = i & 1023;
        int row = j >> 3, of = (j & 7) * 16;
        cpa16(smem_u32(sm + LBOFF + tap * 18432 + row * 144 + of),
              g + (size_t)tap * 32768 + row * 128 + of);
    }
    cp_commit();
}

template<int MT>
__device__ __forceinline__ void mk_addrs(uint32_t smb, uint32_t asz, int warp_m,
        int warp_n, int l, uint32_t aH[][3], uint32_t aL[][3], uint32_t* bOf) {
    #pragma unroll
    for (int mt = 0; mt < MT; mt++) {
        int prow16 = warp_m * MT + mt;
        #pragma unroll
        for (int kw = 0; kw < 3; kw++) {
            int col = (l & 15) + kw - 1;
            uint32_t kpart = (uint32_t)(l >> 4) * 16;
            if ((unsigned)col > 15u) { aH[mt][kw] = smb + kpart; aL[mt][kw] = smb + kpart; }
            else {
                uint32_t base = smb + AHI + (uint32_t)(prow16 * 16 + col) * 144 + kpart;
                aH[mt][kw] = base;
                aL[mt][kw] = base + asz;
            }
        }
    }
    #pragma unroll
    for (int ntp = 0; ntp < 4; ntp++) {
        int nl = warp_n * 64 + ntp * 16 + (l & 7) + ((l >> 4) << 3);
        bOf[ntp] = (uint32_t)nl * 144 + ((l >> 3) & 1) * 16;
    }
}

// kh is RUNTIME (outer loop not unrolled); kw must be a compile-time-constant
// unrolled-loop index so aH[][kw] stays statically indexed (no local memory).
template<int MT, int TERMS, int KC>
__device__ __forceinline__ void gemm_tap(float (*acc)[4],
        const uint32_t aH[][3], const uint32_t aL[][3], const uint32_t* bOf,
        uint32_t bbase, uint32_t akk, int kw) {
    #pragma unroll
    for (int kc = 0; kc < KC; kc++) {
        uint32_t ko = akk + (uint32_t)kc * 32;
        uint32_t ah[MT][4], al[MT][4], bh[4][4];
        #pragma unroll
        for (int mt = 0; mt < MT; mt++) {
            ldsm4(ah[mt], aH[mt][kw] + ko);
            if (TERMS == 2) ldsm4(al[mt], aL[mt][kw] + ko);
        }
        #pragma unroll
        for (int ntp = 0; ntp < 4; ntp++)
            ldsm4(bh[ntp], bbase + bOf[ntp] + (uint32_t)kc * 32);
        #pragma unroll
        for (int mt = 0; mt < MT; mt++)
        #pragma unroll
        for (int ntp = 0; ntp < 4; ntp++) {
            float* c0 = acc[mt * 8 + 2 * ntp];
            float* c1 = acc[mt * 8 + 2 * ntp + 1];
            mma16816(c0, ah[mt], bh[ntp]);  mma16816(c1, ah[mt], bh[ntp] + 2);
            if (TERMS == 2) {
                mma16816(c0, al[mt], bh[ntp]);  mma16816(c1, al[mt], bh[ntp] + 2);
            }
        }
    }
}

__global__ void embed_kernel(const float* __restrict__ x) {
    int idx = blockIdx.x * 256 + threadIdx.x;
    if (idx >= NIMG * 256 * 64) return;
    int c = idx & 63, px = (idx >> 6) & 255, img = idx >> 14;
    int b = img / 28, t = img % 28;
    float v = 0.f;
    if (c < 24) {
        int flat = t * 24 + c;
        v = x[((size_t)(b * 112 + flat / 6) * 256 + px) * 6 + flat % 6];
    }
    g_xeh[idx] = __float2half(v);
}

__global__ void wprep_all(
    const float* __restrict__ wx0f, const float* __restrict__ wx0b,
    const float* __restrict__ wh0f, const float* __restrict__ wh0b,
    const float* __restrict__ wx1f, const float* __restrict__ wx1b,
    const float* __restrict__ wh1f, const float* __restrict__ wh1b) {
    int idx = blockIdx.x * 256 + threadIdx.x;
    if (idx < 524288) g_cst[idx] = 0.f;
    if (idx < 16384)  g_zeroh[idx] = __float2half(0.f);
    if (idx < 1024)   g_grpbar[idx] = 0u;
    if (idx >= 90 * TAPSZ) return;
    int ic = idx & 63, n = (idx >> 6) & 255, unit = idx >> 14;
    const float* w; int IC, u0;
    if (unit < 18)      { w = unit < 9  ? wx0f : wx0b; IC = 24;  u0 = unit < 9  ? 0  : 9;  }
    else if (unit < 36) { w = unit < 27 ? wh0f : wh0b; IC = 64;  u0 = unit < 27 ? 18 : 27; }
    else if (unit < 72) { w = unit < 54 ? wx1f : wx1b; IC = 128; u0 = unit < 54 ? 36 : 54; }
    else                { w = unit < 81 ? wh1f : wh1b; IC = 64;  u0 = unit < 81 ? 72 : 81; }
    int tl = unit - u0;
    int src = tl / 9, rtap = tl % 9, ics = src * 64 + ic;
    int f = n >> 2, g = n & 3;
    float v = (ics < IC) ? w[((size_t)rtap * IC + ics) * 256 + (g * 64 + f)] : 0.f;
    g_w[idx] = __float2half(v);
}

__global__ void zero_states() {
    int idx = blockIdx.x * 256 + threadIdx.x;
    if (idx < 524288) g_cst[idx] = 0.f;
    if (idx < 1024)   g_grpbar[idx] = 0u;
}

template<int NSRC, int KC>
__global__ void __launch_bounds__(256, 1) conv_mma_kernel(
    const fp16* __restrict__ s0h, const fp16* __restrict__ s1h,
    const fp16* __restrict__ wf, const fp16* __restrict__ wb,
    const float* __restrict__ bf_, const float* __restrict__ bb_) {
    extern __shared__ char sm[];
    uint32_t smb = smem_u32(sm);
    int tid = threadIdx.x, l = tid & 31, w = tid >> 5;
    int warp_m = w >> 1, warp_n = w & 1, q = l & 3;
    int img = blockIdx.x, dir = blockIdx.y, ncol = blockIdx.z;
    const fp16* wsel = dir ? wb : wf;
    const float* bias = dir ? bb_ : bf_;
    const int T = NSRC * 9;

    for (int i = tid; i < ZSZ / 16; i += 256)
        *(uint4*)(sm + i * 16) = make_uint4(0, 0, 0, 0);
    fill_A<1>(sm, CASZ, s0h + (size_t)img * 16384, (const fp16*)0, 0, 18, tid);
    prefB(sm, CBOFF, 0, wsel, 0, ncol, tid);
    prefB(sm, CBOFF, 1, wsel, 1, ncol, tid);
    prefB(sm, CBOFF, 2, wsel, 2, ncol, tid);

    uint32_t aH[4][3], aL[4][3], bOf[4];
    mk_addrs<4>(smb, CASZ, warp_m, warp_n, l, aH, aL, bOf);
    float acc[32][4];
    #pragma unroll
    for (int i = 0; i < 32; i++)
        acc[i][0] = acc[i][1] = acc[i][2] = acc[i][3] = 0.f;

    int tap = 0;
    #pragma unroll 1
    for (int u = 0; u < NSRC; u++) {
        #pragma unroll 1
        for (int kh = 0; kh < 3; kh++) {
            uint32_t akk = (uint32_t)kh * 2304;
            #pragma unroll
            for (int kw = 0; kw < 3; kw++) {
                if (tap < T - 2) cp_wait2(); else if (tap == T - 2) cp_wait1(); else cp_wait0();
                __syncthreads();
                if (NSRC == 2 && tap == 9) {
                    fill_A<1>(sm, CASZ, s1h + (size_t)img * 16384, (const fp16*)0, 0, 18, tid);
                    __syncthreads();
                }
                gemm_tap<4, 1, KC>(acc, aH, aL, bOf,
                                   smb + CBOFF + (tap & 3) * 18432, akk, kw);
                __syncthreads();
                if (tap + 3 < T) prefB(sm, CBOFF, (tap + 3) & 3, wsel, tap + 3, ncol, tid);
                tap++;
            }
        }
    }

    size_t xzo = (((size_t)dir * NIMG + img) * 2 + ncol) * 32768;
    #pragma unroll
    for (int mt = 0; mt < 4; mt++) {
        int m = warp_m * 64 + mt * 16 + (l >> 2);
        #pragma unroll
        for (int nt = 0; nt < 8; nt++) {
            float* c = acc[mt * 8 + nt];
            int ng = ncol * 128 + warp_n * 64 + nt * 8 + q * 2;
            float b0 = __ldg(&bias[(ng & 3) * 64 + (ng >> 2)]);
            float b1 = __ldg(&bias[((ng + 1) & 3) * 64 + ((ng + 1) >> 2)]);
            int n4 = warp_n * 16 + nt * 2 + (q >> 1);
            int j = (q & 1) * 2;
            float* p0 = g_xz + xzo + (size_t)n4 * 1024 + m * 4 + j;
            *(float2*)p0 = make_float2(c[0] + b0, c[1] + b1);
            *(float2*)(p0 + 32) = make_float2(c[2] + b0, c[3] + b1);
        }
    }
}

__global__ void __launch_bounds__(256, 1) lstm_persist_kernel(
    const fp16* __restrict__ wf, const fp16* __restrict__ wb,
    fp16* __restrict__ q0h, fp16* __restrict__ q0l,
    fp16* __restrict__ q1h, fp16* __restrict__ q1l) {
    extern __shared__ char sm[];
    uint32_t smb = smem_u32(sm);
    int tid = threadIdx.x, l = tid & 31, w = tid >> 5;
    int warp_m = w >> 1, warp_n = w & 1, q = l & 3;
    int bx = blockIdx.x;
    int dir = bx >> 6, b = (bx >> 2) & 15, hf = (bx >> 1) & 1, ncol = bx & 1;
    const fp16* wsel = dir ? wb : wf;
    fp16* qh = dir ? q1h : q0h;
    fp16* ql = dir ? q1l : q0l;
    unsigned grp = (unsigned)(bx >> 2);

    prefB_all(sm, wsel, ncol, tid);
    for (int i = tid; i < ZSZ / 16; i += 256)
        *(uint4*)(sm + i * 16) = make_uint4(0, 0, 0, 0);

    uint32_t aH[2][3], aL[2][3], bOf[4];
    mk_addrs<2>(smb, LASZ, warp_m, warp_n, l, aH, aL, bOf);
    size_t ctaBase = (size_t)bx * 4096;
    bool lower = !(l & 1);
    cp_wait0();
    __syncthreads();

    #pragma unroll 1
    for (int s = 0; s < 28; s++) {
        int t = dir ? (27 - s) : s;
        int img = b * 28 + t;
        int tprev = dir ? (t + 1) : (t - 1);
        const fp16* hs_ = (s == 0) ? g_zeroh : qh + (size_t)(b * 28 + tprev) * 16384;
        const fp16* ls_ = (s == 0) ? g_zeroh : ql + (size_t)(b * 28 + tprev) * 16384;

        fill_A<2>(sm, LASZ, hs_, ls_, hf * 8, 10, tid);
        __syncthreads();

        float acc[16][4];
        #pragma unroll
        for (int i = 0; i < 16; i++)
            acc[i][0] = acc[i][1] = acc[i][2] = acc[i][3] = 0.f;
        #pragma unroll 1
        for (int kh = 0; kh < 3; kh++) {
            uint32_t akk = (uint32_t)kh * 2304;
            uint32_t bb = smb + LBOFF + (uint32_t)kh * 3 * 18432;
            #pragma unroll
            for (int kw = 0; kw < 3; kw++)
                gemm_tap<2, 2, 4>(acc, aH, aL, bOf, bb + (uint32_t)kw * 18432, akk, kw);
        }
        __syncthreads();

        size_t xzo = (((size_t)dir * NIMG + img) * 2 + ncol) * 32768;
        #pragma unroll
        for (int mt = 0; mt < 2; mt++) {
            int mbase = warp_m * 32 + mt * 16 + (l >> 2);
            #pragma unroll
            for (int nt = 0; nt < 8; nt++) {
                float* c = acc[mt * 8 + nt];
                float o0 = __shfl_xor_sync(0xffffffffu, c[0], 1);
                float o1 = __shfl_xor_sync(0xffffffffu, c[1], 1);
                float o2 = __shfl_xor_sync(0xffffffffu, c[2], 1);
                float o3 = __shfl_xor_sync(0xffffffffu, c[3], 1);
                float iv, fv, gv, ov;
                int m;
                if (lower) { iv = c[0]; fv = c[1]; gv = o0;  ov = o1;  m = mbase; }
                else       { iv = o2;  fv = o3;  gv = c[2]; ov = c[3]; m = mbase + 8; }
                int chp = q >> 1;
                int n4 = warp_n * 16 + nt * 2 + chp;
                int pxg = hf * 128 + m;
                float4 z = *(const float4*)(g_xz + xzo + (size_t)n4 * 1024 + pxg * 4);
                iv = sigm(iv + z.x); fv = sigm(fv + z.y);
                gv = tanhf(gv + z.z); ov = sigm(ov + z.w);
                float* cs = g_cst + ctaBase + w * 512 + (mt * 8 + nt) * 32 + l;
                float cc = fv * (*cs) + iv * gv;
                *cs = cc;
                float hv = ov * tanhf(cc);
                fp16 hb = __float2half(hv);
                float lr = hv - __half2float(hb);
                int chc = warp_n * 16 + nt * 2 + chp;
                *(fp16*)(sm + AHI + m * 64 + chc * 2) = hb;
                *(fp16*)(sm + AHI + 8192 + m * 64 + chc * 2) = __float2half(lr);
            }
        }
        __syncthreads();

        {
            int px = tid >> 1, part = tid & 1;
            const uint4* sh_ = (const uint4*)(sm + AHI + px * 64 + part * 32);
            const uint4* sl_ = (const uint4*)(sm + AHI + 8192 + px * 64 + part * 32);
            uint4 h0 = sh_[0], h1 = sh_[1];
            uint4 l0 = sl_[0], l1 = sl_[1];
            size_t qidx = ((size_t)img * 256 + hf * 128 + px) * 64 + ncol * 32 + part * 16;
            *(uint4*)(qh + qidx) = h0;
            *(uint4*)(qh + qidx + 8) = h1;
            *(uint4*)(ql + qidx) = l0;
            *(uint4*)(ql + qidx + 8) = l1;
        }

        if (s < 27) {
            __syncthreads();
            if (tid == 0) {
                __threadfence();
                atomicAdd(&g_grpbar[grp * 32], 1u);
                unsigned target = 4u * (unsigned)(s + 1);
                volatile unsigned* bc = &g_grpbar[grp * 32];
                while (*bc < target) __nanosleep(32);
                __threadfence();
            }
            __syncthreads();
        }
    }
}

__global__ void __launch_bounds__(256) out_conv_kernel(
    const fp16* __restrict__ d0h, const fp16* __restrict__ d0l,
    const fp16* __restrict__ d1h, const fp16* __restrict__ d1l,
    const float* __restrict__ wout, const float* __restrict__ bout,
    float* __restrict__ out) {
    __shared__ float sh[3 * 16 * 128];
    __shared__ float ps[256];
    int n = blockIdx.x / 16, h = blockIdx.x % 16, tid = threadIdx.x;
    for (int i = tid; i < 3 * 16 * 128; i += 256) {
        int r = i / 2048, rem = i - r * 2048, c = rem >> 7, ch = rem & 127;
        int row = h - 1 + r;
        float v = 0.f;
        if (row >= 0 && row < 16) {
            size_t idx = ((size_t)n * 256 + row * 16 + c) * 64 + (ch & 63);
            if (ch < 64) v = __half2float(d0h[idx]) + __half2float(d0l[idx]);
            else         v = __half2float(d1h[idx]) + __half2float(d1l[idx]);
        }
        sh[i] = v;
    }
    __syncthreads();
    int p = tid >> 4, qq = tid & 15;
    float partial = 0.f;
    for (int kh = 0; kh < 3; kh++)
        for (int kw = 0; kw < 3; kw++) {
            int iw = p + kw - 1;
            if (iw < 0 || iw >= 16) continue;
            #pragma unroll
            for (int j = 0; j < 8; j++) {
                int ic = qq * 8 + j;
                partial += sh[(kh * 16 + iw) * 128 + ic] * wout[(kh * 3 + kw) * 128 + ic];
            }
        }
    ps[tid] = partial;
    __syncthreads();
    if (qq == 0) {
        float sum = bout[0];
        #pragma unroll
        for (int j = 0; j < 16; j++) sum += ps[p * 16 + j];
        out[((size_t)n * 16 + h) * 16 + p] = sum;
    }
}

extern "C" void kernel_launch(void* const* d_in, const int* in_sizes, int n_in,
                              void* d_out, int out_size) {
    const float* x    = (const float*)d_in[0];
    const float* wx0f = (const float*)d_in[1];
    const float* wh0f = (const float*)d_in[2];
    const float* b0f  = (const float*)d_in[3];
    const float* wx0b = (const float*)d_in[4];
    const float* wh0b = (const float*)d_in[5];
    const float* b0b  = (const float*)d_in[6];
    const float* wx1f = (const float*)d_in[7];
    const float* wh1f = (const float*)d_in[8];
    const float* b1f  = (const float*)d_in[9];
    const float* wx1b = (const float*)d_in[10];
    const float* wh1b = (const float*)d_in[11];
    const float* b1b  = (const float*)d_in[12];
    const float* wout = (const float*)d_in[13];
    const float* bout = (const float*)d_in[14];
    float* out = (float*)d_out;

    cudaFuncSetAttribute((const void*)conv_mma_kernel<1,2>, cudaFuncAttributeMaxDynamicSharedMemorySize, CSMEM);
    cudaFuncSetAttribute((const void*)conv_mma_kernel<2,4>, cudaFuncAttributeMaxDynamicSharedMemorySize, CSMEM);
    cudaFuncSetAttribute((const void*)lstm_persist_kernel, cudaFuncAttributeMaxDynamicSharedMemorySize, LSMEM);

    fp16 *wg, *xeh, *q0h, *q0l, *q1h, *q1l;
    cudaGetSymbolAddress((void**)&wg, g_w);
    cudaGetSymbolAddress((void**)&xeh, g_xeh);
    cudaGetSymbolAddress((void**)&q0h, g_q0h);
    cudaGetSymbolAddress((void**)&q0l, g_q0l);
    cudaGetSymbolAddress((void**)&q1h, g_q1h);
    cudaGetSymbolAddress((void**)&q1l, g_q1l);

    // capture slot is launch #3 -> lstm layer 0 stays there
    wprep_all<<<(90*TAPSZ + 255)/256, 256>>>(wx0f, wx0b, wh0f, wh0b,
                                             wx1f, wx1b, wh1f, wh1b);          // 0 (+zero)
    embed_kernel<<<(NIMG*256*64 + 255)/256, 256>>>(x);                         // 1
    dim3 cgrid(NIMG, 2, 2);
    conv_mma_kernel<1,2><<<cgrid, 256, CSMEM>>>(xeh, xeh,
        wg + (size_t)0*TAPSZ, wg + (size_t)9*TAPSZ, b0f, b0b);                 // 2
    lstm_persist_kernel<<<128, 256, LSMEM>>>(
        wg + (size_t)18*TAPSZ, wg + (size_t)27*TAPSZ, q0h, q0l, q1h, q1l);     // 3 <- captured
    zero_states<<<2048, 256>>>();                                              // 4
    conv_mma_kernel<2,4><<<cgrid, 256, CSMEM>>>(q0h, q1h,
        wg + (size_t)36*TAPSZ, wg + (size_t)54*TAPSZ, b1f, b1b);               // 5
    lstm_persist_kernel<<<128, 256, LSMEM>>>(
        wg + (size_t)72*TAPSZ, wg + (size_t)81*TAPSZ, q0h, q0l, q1h, q1l);     // 6
    out_conv_kernel<<<NIMG*16, 256>>>(q0h, q0l, q1h, q1l, wout, bout, out);    // 7
}

// round 14
// speedup vs baseline: 1.1670x; 1.1670x over previous
#include <cuda_runtime.h>
#include <cuda_fp16.h>
#include <stdint.h>
#include <math.h>

typedef __half fp16;

#define NIMG 448
#define TAPSZ 16384
#define ZSZ   4864
#define AHI   4864
#define LASZ  23040
#define LBOFF (AHI + 2*LASZ)           // 50944
#define LSMEM (LBOFF + 9*18432)        // 216832
#define CASZ  41472
#define CBOFF (AHI + CASZ)             // 46336
#define CSMEM (CBOFF + 4*18432)        // 120064

__device__ fp16  g_xeh[(size_t)NIMG*256*64];
__device__ float g_xz[(size_t)2*NIMG*2*32768];   // [dir][img][ncol][n4(32)][px(256)][4]
__device__ fp16  g_q0h[(size_t)NIMG*256*64], g_q0l[(size_t)NIMG*256*64];
__device__ fp16  g_q1h[(size_t)NIMG*256*64], g_q1l[(size_t)NIMG*256*64];
__device__ float g_cst[524288];
__device__ fp16  g_w[(size_t)90*TAPSZ];
__device__ fp16  g_zeroh[16384];
__device__ unsigned g_grpbar[1024];

__device__ __forceinline__ uint32_t smem_u32(const void* p) {
    uint32_t a;
    asm("{ .reg .u64 t; cvta.to.shared.u64 t, %1; cvt.u32.u64 %0, t; }" : "=r"(a) : "l"(p));
    return a;
}
__device__ __forceinline__ void ldsm4(uint32_t* r, uint32_t addr) {
    asm volatile("ldmatrix.sync.aligned.m8n8.x4.shared.b16 {%0,%1,%2,%3}, [%4];"
        : "=r"(r[0]), "=r"(r[1]), "=r"(r[2]), "=r"(r[3]) : "r"(addr));
}
__device__ __forceinline__ void mma16816(float* c, const uint32_t* a, const uint32_t* b) {
    asm volatile("mma.sync.aligned.m16n8k16.row.col.f32.f16.f16.f32 "
        "{%0,%1,%2,%3}, {%4,%5,%6,%7}, {%8,%9}, {%0,%1,%2,%3};"
        : "+f"(c[0]), "+f"(c[1]), "+f"(c[2]), "+f"(c[3])
        : "r"(a[0]), "r"(a[1]), "r"(a[2]), "r"(a[3]), "r"(b[0]), "r"(b[1]));
}
__device__ __forceinline__ void cpa16(uint32_t dst, const void* src) {
    asm volatile("cp.async.cg.shared.global [%0], [%1], 16;" :: "r"(dst), "l"(src) : "memory");
}
__device__ __forceinline__ void cp_commit() { asm volatile("cp.async.commit_group;" ::: "memory"); }
__device__ __forceinline__ void cp_wait2()  { asm volatile("cp.async.wait_group 2;" ::: "memory"); }
__device__ __forceinline__ void cp_wait1()  { asm volatile("cp.async.wait_group 1;" ::: "memory"); }
__device__ __forceinline__ void cp_wait0()  { asm volatile("cp.async.wait_group 0;" ::: "memory"); }
__device__ __forceinline__ float sigm(float x) { return __fdividef(1.f, 1.f + __expf(-x)); }

template<int TERMS, int NTHR>
__device__ __forceinline__ void fill_A(char* sm, uint32_t asz,
        const fp16* hsrc, const fp16* lsrc, int r0, int nrows, int tid) {
    const uint4* hv = (const uint4*)hsrc;
    const uint4* lv = (const uint4*)lsrc;
    const uint4 z = make_uint4(0, 0, 0, 0);
    int tot = nrows * 16 * 8;
    for (int i = tid; i < tot; i += NTHR) {
        int ch = i & 7, p = i >> 3;
        int hr = p >> 4, c = p & 15;
        int row = r0 - 1 + hr;
        bool v = (row >= 0 && row < 16);
        int gi = (row * 16 + c) * 8 + ch;
        uint4 hval = v ? hv[gi] : z;
        *(uint4*)(sm + AHI + p * 144 + ch * 16) = hval;
        if (TERMS == 2) {
            uint4 lval = v ? lv[gi] : z;
            *(uint4*)(sm + AHI + asz + p * 144 + ch * 16) = lval;
        }
    }
}

__device__ __forceinline__ void prefB(char* sm, uint32_t boff, int slot,
        const fp16* w, int tap, int ncol, int tid) {
    char* dh = sm + boff + slot * 18432;
    const char* g = (const char*)w + (size_t)tap * 32768 + (size_t)ncol * 16384;
    #pragma unroll
    for (int jj = 0; jj < 4; jj++) {
        int j = tid * 4 + jj;
        int row = j >> 3, of = (j & 7) * 16;
        cpa16(smem_u32(dh + row * 144 + of), g + row * 128 + of);
    }
    cp_commit();
}

__device__ __forceinline__ void prefB_all(char* sm, const fp16* w, int ncol, int tid) {
    const char* g = (const char*)w + (size_t)ncol * 16384;
    for (int i = tid; i < 9216; i += 512) {
        int tap = i >> 10, j = i & 1023;
        int row = j >> 3, of = (j & 7) * 16;
        cpa16(smem_u32(sm + LBOFF + tap * 18432 + row * 144 + of),
              g + (size_t)tap * 32768 + row * 128 + of);
    }
    cp_commit();
}

// MT m-tiles of 16, NTP n-tiles of 16; warp_n spans NTP*16 columns
template<int MT, int NTP>
__device__ __forceinline__ void mk_addrs(uint32_t smb, uint32_t asz, int warp_m,
        int warp_n, int l, uint32_t aH[][3], uint32_t aL[][3], uint32_t* bOf) {
    #pragma unroll
    for (int mt = 0; mt < MT; mt++) {
        int prow16 = warp_m * MT + mt;
        #pragma unroll
        for (int kw = 0; kw < 3; kw++) {
            int col = (l & 15) + kw - 1;
            uint32_t kpart = (uint32_t)(l >> 4) * 16;
            if ((unsigned)col > 15u) { aH[mt][kw] = smb + kpart; aL[mt][kw] = smb + kpart; }
            else {
                uint32_t base = smb + AHI + (uint32_t)(prow16 * 16 + col) * 144 + kpart;
                aH[mt][kw] = base;
                aL[mt][kw] = base + asz;
            }
        }
    }
    #pragma unroll
    for (int ntp = 0; ntp < NTP; ntp++) {
        int nl = warp_n * (NTP * 16) + ntp * 16 + (l & 7) + ((l >> 4) << 3);
        bOf[ntp] = (uint32_t)nl * 144 + ((l >> 3) & 1) * 16;
    }
}

template<int MT, int NTP, int TERMS, int KC>
__device__ __forceinline__ void gemm_tap(float (*acc)[4],
        const uint32_t aH[][3], const uint32_t aL[][3], const uint32_t* bOf,
        uint32_t bbase, uint32_t akk, int kw) {
    #pragma unroll
    for (int kc = 0; kc < KC; kc++) {
        uint32_t ko = akk + (uint32_t)kc * 32;
        uint32_t ah[MT][4], al[MT][4], bh[NTP][4];
        #pragma unroll
        for (int mt = 0; mt < MT; mt++) {
            ldsm4(ah[mt], aH[mt][kw] + ko);
            if (TERMS == 2) ldsm4(al[mt], aL[mt][kw] + ko);
        }
        #pragma unroll
        for (int ntp = 0; ntp < NTP; ntp++)
            ldsm4(bh[ntp], bbase + bOf[ntp] + (uint32_t)kc * 32);
        #pragma unroll
        for (int mt = 0; mt < MT; mt++)
        #pragma unroll
        for (int ntp = 0; ntp < NTP; ntp++) {
            float* c0 = acc[(mt * NTP + ntp) * 2];
            float* c1 = acc[(mt * NTP + ntp) * 2 + 1];
            mma16816(c0, ah[mt], bh[ntp]);  mma16816(c1, ah[mt], bh[ntp] + 2);
            if (TERMS == 2) {
                mma16816(c0, al[mt], bh[ntp]);  mma16816(c1, al[mt], bh[ntp] + 2);
            }
        }
    }
}

__global__ void embed_kernel(const float* __restrict__ x) {
    int idx = blockIdx.x * 256 + threadIdx.x;
    if (idx >= NIMG * 256 * 64) return;
    int c = idx & 63, px = (idx >> 6) & 255, img = idx >> 14;
    int b = img / 28, t = img % 28;
    float v = 0.f;
    if (c < 24) {
        int flat = t * 24 + c;
        v = x[((size_t)(b * 112 + flat / 6) * 256 + px) * 6 + flat % 6];
    }
    g_xeh[idx] = __float2half(v);
}

__global__ void wprep_all(
    const float* __restrict__ wx0f, const float* __restrict__ wx0b,
    const float* __restrict__ wh0f, const float* __restrict__ wh0b,
    const float* __restrict__ wx1f, const float* __restrict__ wx1b,
    const float* __restrict__ wh1f, const float* __restrict__ wh1b) {
    int idx = blockIdx.x * 256 + threadIdx.x;
    if (idx < 524288) g_cst[idx] = 0.f;
    if (idx < 16384)  g_zeroh[idx] = __float2half(0.f);
    if (idx < 1024)   g_grpbar[idx] = 0u;
    if (idx >= 90 * TAPSZ) return;
    int ic = idx & 63, n = (idx >> 6) & 255, unit = idx >> 14;
    const float* w; int IC, u0;
    if (unit < 18)      { w = unit < 9  ? wx0f : wx0b; IC = 24;  u0 = unit < 9  ? 0  : 9;  }
    else if (unit < 36) { w = unit < 27 ? wh0f : wh0b; IC = 64;  u0 = unit < 27 ? 18 : 27; }
    else if (unit < 72) { w = unit < 54 ? wx1f : wx1b; IC = 128; u0 = unit < 54 ? 36 : 54; }
    else                { w = unit < 81 ? wh1f : wh1b; IC = 64;  u0 = unit < 81 ? 72 : 81; }
    int tl = unit - u0;
    int src = tl / 9, rtap = tl % 9, ics = src * 64 + ic;
    int f = n >> 2, g = n & 3;
    float v = (ics < IC) ? w[((size_t)rtap * IC + ics) * 256 + (g * 64 + f)] : 0.f;
    g_w[idx] = __float2half(v);
}

__global__ void zero_states() {
    int idx = blockIdx.x * 256 + threadIdx.x;
    if (idx < 524288) g_cst[idx] = 0.f;
    if (idx < 1024)   g_grpbar[idx] = 0u;
}

template<int NSRC, int KC>
__global__ void __launch_bounds__(256, 1) conv_mma_kernel(
    const fp16* __restrict__ s0h, const fp16* __restrict__ s1h,
    const fp16* __restrict__ wf, const fp16* __restrict__ wb,
    const float* __restrict__ bf_, const float* __restrict__ bb_) {
    extern __shared__ char sm[];
    uint32_t smb = smem_u32(sm);
    int tid = threadIdx.x, l = tid & 31, w = tid >> 5;
    int warp_m = w >> 1, warp_n = w & 1, q = l & 3;
    int img = blockIdx.x, dir = blockIdx.y, ncol = blockIdx.z;
    const fp16* wsel = dir ? wb : wf;
    const float* bias = dir ? bb_ : bf_;
    const int T = NSRC * 9;

    for (int i = tid; i < ZSZ / 16; i += 256)
        *(uint4*)(sm + i * 16) = make_uint4(0, 0, 0, 0);
    fill_A<1, 256>(sm, CASZ, s0h + (size_t)img * 16384, (const fp16*)0, 0, 18, tid);
    prefB(sm, CBOFF, 0, wsel, 0, ncol, tid);
    prefB(sm, CBOFF, 1, wsel, 1, ncol, tid);
    prefB(sm, CBOFF, 2, wsel, 2, ncol, tid);

    uint32_t aH[4][3], aL[4][3], bOf[4];
    mk_addrs<4, 4>(smb, CASZ, warp_m, warp_n, l, aH, aL, bOf);
    float acc[32][4];
    #pragma unroll
    for (int i = 0; i < 32; i++)
        acc[i][0] = acc[i][1] = acc[i][2] = acc[i][3] = 0.f;

    int tap = 0;
    #pragma unroll 1
    for (int u = 0; u < NSRC; u++) {
        #pragma unroll 1
        for (int kh = 0; kh < 3; kh++) {
            uint32_t akk = (uint32_t)kh * 2304;
            #pragma unroll
            for (int kw = 0; kw < 3; kw++) {
                if (tap < T - 2) cp_wait2(); else if (tap == T - 2) cp_wait1(); else cp_wait0();
                __syncthreads();
                if (NSRC == 2 && tap == 9) {
                    fill_A<1, 256>(sm, CASZ, s1h + (size_t)img * 16384, (const fp16*)0, 0, 18, tid);
                    __syncthreads();
                }
                gemm_tap<4, 4, 1, KC>(acc, aH, aL, bOf,
                                      smb + CBOFF + (tap & 3) * 18432, akk, kw);
                __syncthreads();
                if (tap + 3 < T) prefB(sm, CBOFF, (tap + 3) & 3, wsel, tap + 3, ncol, tid);
                tap++;
            }
        }
    }

    size_t xzo = (((size_t)dir * NIMG + img) * 2 + ncol) * 32768;
    #pragma unroll
    for (int mt = 0; mt < 4; mt++) {
        int m = warp_m * 64 + mt * 16 + (l >> 2);
        #pragma unroll
        for (int nt = 0; nt < 8; nt++) {
            float* c = acc[mt * 8 + nt];
            int ng = ncol * 128 + warp_n * 64 + nt * 8 + q * 2;
            float b0 = __ldg(&bias[(ng & 3) * 64 + (ng >> 2)]);
            float b1 = __ldg(&bias[((ng + 1) & 3) * 64 + ((ng + 1) >> 2)]);
            int n4 = warp_n * 16 + nt * 2 + (q >> 1);
            int j = (q & 1) * 2;
            float* p0 = g_xz + xzo + (size_t)n4 * 1024 + m * 4 + j;
            *(float2*)p0 = make_float2(c[0] + b0, c[1] + b1);
            *(float2*)(p0 + 32) = make_float2(c[2] + b0, c[3] + b1);
        }
    }
}

// 512-thread persistent LSTM: 16 warps, each M=32 x N=32 (MT=2, NTP=2)
__global__ void __launch_bounds__(512, 1) lstm_persist_kernel(
    const fp16* __restrict__ wf, const fp16* __restrict__ wb,
    fp16* __restrict__ q0h, fp16* __restrict__ q0l,
    fp16* __restrict__ q1h, fp16* __restrict__ q1l) {
    extern __shared__ char sm[];
    uint32_t smb = smem_u32(sm);
    int tid = threadIdx.x, l = tid & 31, w = tid >> 5;
    int warp_m = w >> 2, warp_n = w & 3, q = l & 3;
    int bx = blockIdx.x;
    int dir = bx >> 6, b = (bx >> 2) & 15, hf = (bx >> 1) & 1, ncol = bx & 1;
    const fp16* wsel = dir ? wb : wf;
    fp16* qh = dir ? q1h : q0h;
    fp16* ql = dir ? q1l : q0l;
    unsigned grp = (unsigned)(bx >> 2);

    prefB_all(sm, wsel, ncol, tid);
    for (int i = tid; i < ZSZ / 16; i += 512)
        *(uint4*)(sm + i * 16) = make_uint4(0, 0, 0, 0);

    uint32_t aH[2][3], aL[2][3], bOf[2];
    mk_addrs<2, 2>(smb, LASZ, warp_m, warp_n, l, aH, aL, bOf);
    size_t ctaBase = (size_t)bx * 4096;
    bool lower = !(l & 1);
    cp_wait0();
    __syncthreads();

    #pragma unroll 1
    for (int s = 0; s < 28; s++) {
        int t = dir ? (27 - s) : s;
        int img = b * 28 + t;
        int tprev = dir ? (t + 1) : (t - 1);
        const fp16* hs_ = (s == 0) ? g_zeroh : qh + (size_t)(b * 28 + tprev) * 16384;
        const fp16* ls_ = (s == 0) ? g_zeroh : ql + (size_t)(b * 28 + tprev) * 16384;

        fill_A<2, 512>(sm, LASZ, hs_, ls_, hf * 8, 10, tid);
        __syncthreads();

        float acc[8][4];
        #pragma unroll
        for (int i = 0; i < 8; i++)
            acc[i][0] = acc[i][1] = acc[i][2] = acc[i][3] = 0.f;
        #pragma unroll 1
        for (int kh = 0; kh < 3; kh++) {
            uint32_t akk = (uint32_t)kh * 2304;
            uint32_t bb = smb + LBOFF + (uint32_t)kh * 3 * 18432;
            #pragma unroll
            for (int kw = 0; kw < 3; kw++)
                gemm_tap<2, 2, 2, 4>(acc, aH, aL, bOf, bb + (uint32_t)kw * 18432, akk, kw);
        }
        __syncthreads();

        size_t xzo = (((size_t)dir * NIMG + img) * 2 + ncol) * 32768;
        #pragma unroll
        for (int mt = 0; mt < 2; mt++) {
            int mbase = warp_m * 32 + mt * 16 + (l >> 2);
            #pragma unroll
            for (int nt = 0; nt < 4; nt++) {
                float* c = acc[mt * 4 + nt];
                float o0 = __shfl_xor_sync(0xffffffffu, c[0], 1);
                float o1 = __shfl_xor_sync(0xffffffffu, c[1], 1);
                float o2 = __shfl_xor_sync(0xffffffffu, c[2], 1);
                float o3 = __shfl_xor_sync(0xffffffffu, c[3], 1);
                float iv, fv, gv, ov;
                int m;
                if (lower) { iv = c[0]; fv = c[1]; gv = o0;  ov = o1;  m = mbase; }
                else       { iv = o2;  fv = o3;  gv = c[2]; ov = c[3]; m = mbase + 8; }
                int chp = q >> 1;
                int n4 = warp_n * 8 + nt * 2 + chp;
                int pxg = hf * 128 + m;
                float4 z = *(const float4*)(g_xz + xzo + (size_t)n4 * 1024 + pxg * 4);
                iv = sigm(iv + z.x); fv = sigm(fv + z.y);
                gv = tanhf(gv + z.z); ov = sigm(ov + z.w);
                float* cs = g_cst + ctaBase + w * 256 + (mt * 4 + nt) * 32 + l;
                float cc = fv * (*cs) + iv * gv;
                *cs = cc;
                float hv = ov * tanhf(cc);
                fp16 hb = __float2half(hv);
                float lr = hv - __half2float(hb);
                int chc = warp_n * 8 + nt * 2 + chp;
                *(fp16*)(sm + AHI + m * 64 + chc * 2) = hb;
                *(fp16*)(sm + AHI + 8192 + m * 64 + chc * 2) = __float2half(lr);
            }
        }
        __syncthreads();

        {
            int px = tid >> 2, part = tid & 3;
            uint4 h0 = *(const uint4*)(sm + AHI + px * 64 + part * 16);
            uint4 l0 = *(const uint4*)(sm + AHI + 8192 + px * 64 + part * 16);
            size_t qidx = ((size_t)img * 256 + hf * 128 + px) * 64 + ncol * 32 + part * 8;
            *(uint4*)(qh + qidx) = h0;
            *(uint4*)(ql + qidx) = l0;
        }

        if (s < 27) {
            __syncthreads();
            if (tid == 0) {
                __threadfence();
                atomicAdd(&g_grpbar[grp * 32], 1u);
                unsigned target = 4u * (unsigned)(s + 1);
                volatile unsigned* bc = &g_grpbar[grp * 32];
                while (*bc < target) __nanosleep(32);
                __threadfence();
            }
            __syncthreads();
        }
    }
}

__global__ void __launch_bounds__(256) out_conv_kernel(
    const fp16* __restrict__ d0h, const fp16* __restrict__ d0l,
    const fp16* __restrict__ d1h, const fp16* __restrict__ d1l,
    const float* __restrict__ wout, const float* __restrict__ bout,
    float* __restrict__ out) {
    __shared__ float sh[3 * 16 * 128];
    __shared__ float ps[256];
    int n = blockIdx.x / 16, h = blockIdx.x % 16, tid = threadIdx.x;
    for (int i = tid; i < 3 * 16 * 128; i += 256) {
        int r = i / 2048, rem = i - r * 2048, c = rem >> 7, ch = rem & 127;
        int row = h - 1 + r;
        float v = 0.f;
        if (row >= 0 && row < 16) {
            size_t idx = ((size_t)n * 256 + row * 16 + c) * 64 + (ch & 63);
            if (ch < 64) v = __half2float(d0h[idx]) + __half2float(d0l[idx]);
            else         v = __half2float(d1h[idx]) + __half2float(d1l[idx]);
        }
        sh[i] = v;
    }
    __syncthreads();
    int p = tid >> 4, qq = tid & 15;
    float partial = 0.f;
    for (int kh = 0; kh < 3; kh++)
        for (int kw = 0; kw < 3; kw++) {
            int iw = p + kw - 1;
            if (iw < 0 || iw >= 16) continue;
            #pragma unroll
            for (int j = 0; j < 8; j++) {
                int ic = qq * 8 + j;
                partial += sh[(kh * 16 + iw) * 128 + ic] * wout[(kh * 3 + kw) * 128 + ic];
            }
        }
    ps[tid] = partial;
    __syncthreads();
    if (qq == 0) {
        float sum = bout[0];
        #pragma unroll
        for (int j = 0; j < 16; j++) sum += ps[p * 16 + j];
        out[((size_t)n * 16 + h) * 16 + p] = sum;
    }
}

extern "C" void kernel_launch(void* const* d_in, const int* in_sizes, int n_in,
                              void* d_out, int out_size) {
    const float* x    = (const float*)d_in[0];
    const float* wx0f = (const float*)d_in[1];
    const float* wh0f = (const float*)d_in[2];
    const float* b0f  = (const float*)d_in[3];
    const float* wx0b = (const float*)d_in[4];
    const float* wh0b = (const float*)d_in[5];
    const float* b0b  = (const float*)d_in[6];
    const float* wx1f = (const float*)d_in[7];
    const float* wh1f = (const float*)d_in[8];
    const float* b1f  = (const float*)d_in[9];
    const float* wx1b = (const float*)d_in[10];
    const float* wh1b = (const float*)d_in[11];
    const float* b1b  = (const float*)d_in[12];
    const float* wout = (const float*)d_in[13];
    const float* bout = (const float*)d_in[14];
    float* out = (float*)d_out;

    cudaFuncSetAttribute((const void*)conv_mma_kernel<1,2>, cudaFuncAttributeMaxDynamicSharedMemorySize, CSMEM);
    cudaFuncSetAttribute((const void*)conv_mma_kernel<2,4>, cudaFuncAttributeMaxDynamicSharedMemorySize, CSMEM);
    cudaFuncSetAttribute((const void*)lstm_persist_kernel, cudaFuncAttributeMaxDynamicSharedMemorySize, LSMEM);

    fp16 *wg, *xeh, *q0h, *q0l, *q1h, *q1l;
    cudaGetSymbolAddress((void**)&wg, g_w);
    cudaGetSymbolAddress((void**)&xeh, g_xeh);
    cudaGetSymbolAddress((void**)&q0h, g_q0h);
    cudaGetSymbolAddress((void**)&q0l, g_q0l);
    cudaGetSymbolAddress((void**)&q1h, g_q1h);
    cudaGetSymbolAddress((void**)&q1l, g_q1l);

    // capture slot is launch #3 -> lstm layer 0 stays there
    wprep_all<<<(90*TAPSZ + 255)/256, 256>>>(wx0f, wx0b, wh0f, wh0b,
                                             wx1f, wx1b, wh1f, wh1b);          // 0 (+zero)
    embed_kernel<<<(NIMG*256*64 + 255)/256, 256>>>(x);                         // 1
    dim3 cgrid(NIMG, 2, 2);
    conv_mma_kernel<1,2><<<cgrid, 256, CSMEM>>>(xeh, xeh,
        wg + (size_t)0*TAPSZ, wg + (size_t)9*TAPSZ, b0f, b0b);                 // 2
    lstm_persist_kernel<<<128, 512, LSMEM>>>(
        wg + (size_t)18*TAPSZ, wg + (size_t)27*TAPSZ, q0h, q0l, q1h, q1l);     // 3 <- captured
    zero_states<<<2048, 256>>>();                                              // 4
    conv_mma_kernel<2,4><<<cgrid, 256, CSMEM>>>(q0h, q1h,
        wg + (size_t)36*TAPSZ, wg + (size_t)54*TAPSZ, b1f, b1b);               // 5
    lstm_persist_kernel<<<128, 512, LSMEM>>>(
        wg + (size_t)72*TAPSZ, wg + (size_t)81*TAPSZ, q0h, q0l, q1h, q1l);     // 6
    out_conv_kernel<<<NIMG*16, 256>>>(q0h, q0l, q1h, q1l, wout, bout, out);    // 7
}

// round 15
// speedup vs baseline: 1.2546x; 1.0750x over previous
#include <cuda_runtime.h>
#include <cuda_fp16.h>
#include <stdint.h>
#include <math.h>

typedef __half fp16;

#define NIMG 448
#define TAPSZ 16384
#define ZSZ   4864
#define AHI   4864
#define LASZ  23040
#define LBOFF (AHI + 2*LASZ)           // 50944
#define LSMEM (LBOFF + 9*18432)        // 216832
#define CASZ  41472
#define CBOFF (AHI + CASZ)             // 46336
#define CSMEM (CBOFF + 4*18432)        // 120064

__device__ fp16  g_xeh[(size_t)NIMG*256*64];
__device__ float g_xz[(size_t)2*NIMG*2*32768];   // [dir][img][ncol][n4(32)][px(256)][4]
__device__ fp16  g_q0h[(size_t)NIMG*256*64], g_q0l[(size_t)NIMG*256*64];
__device__ fp16  g_q1h[(size_t)NIMG*256*64], g_q1l[(size_t)NIMG*256*64];
__device__ float g_cst[524288];
__device__ fp16  g_w[(size_t)90*TAPSZ];
__device__ fp16  g_zeroh[16384];
__device__ unsigned g_grpbar[1024];

__device__ __forceinline__ uint32_t smem_u32(const void* p) {
    uint32_t a;
    asm("{ .reg .u64 t; cvta.to.shared.u64 t, %1; cvt.u32.u64 %0, t; }" : "=r"(a) : "l"(p));
    return a;
}
__device__ __forceinline__ void ldsm4(uint32_t* r, uint32_t addr) {
    asm volatile("ldmatrix.sync.aligned.m8n8.x4.shared.b16 {%0,%1,%2,%3}, [%4];"
        : "=r"(r[0]), "=r"(r[1]), "=r"(r[2]), "=r"(r[3]) : "r"(addr));
}
__device__ __forceinline__ void mma16816(float* c, const uint32_t* a, const uint32_t* b) {
    asm volatile("mma.sync.aligned.m16n8k16.row.col.f32.f16.f16.f32 "
        "{%0,%1,%2,%3}, {%4,%5,%6,%7}, {%8,%9}, {%0,%1,%2,%3};"
        : "+f"(c[0]), "+f"(c[1]), "+f"(c[2]), "+f"(c[3])
        : "r"(a[0]), "r"(a[1]), "r"(a[2]), "r"(a[3]), "r"(b[0]), "r"(b[1]));
}
__device__ __forceinline__ void cpa16(uint32_t dst, const void* src) {
    asm volatile("cp.async.cg.shared.global [%0], [%1], 16;" :: "r"(dst), "l"(src) : "memory");
}
__device__ __forceinline__ void cp_commit() { asm volatile("cp.async.commit_group;" ::: "memory"); }
__device__ __forceinline__ void cp_wait2()  { asm volatile("cp.async.wait_group 2;" ::: "memory"); }
__device__ __forceinline__ void cp_wait1()  { asm volatile("cp.async.wait_group 1;" ::: "memory"); }
__device__ __forceinline__ void cp_wait0()  { asm volatile("cp.async.wait_group 0;" ::: "memory"); }
__device__ __forceinline__ void pref_l1(const void* p) {
    asm volatile("prefetch.global.L1 [%0];" :: "l"(p));
}
__device__ __forceinline__ float sigm(float x) { return __fdividef(1.f, 1.f + __expf(-x)); }

template<int TERMS, int NTHR>
__device__ __forceinline__ void fill_A(char* sm, uint32_t asz,
        const fp16* hsrc, const fp16* lsrc, int r0, int nrows, int tid) {
    const uint4* hv = (const uint4*)hsrc;
    const uint4* lv = (const uint4*)lsrc;
    const uint4 z = make_uint4(0, 0, 0, 0);
    int tot = nrows * 16 * 8;
    for (int i = tid; i < tot; i += NTHR) {
        int ch = i & 7, p = i >> 3;
        int hr = p >> 4, c = p & 15;
        int row = r0 - 1 + hr;
        bool v = (row >= 0 && row < 16);
        int gi = (row * 16 + c) * 8 + ch;
        uint4 hval = v ? hv[gi] : z;
        *(uint4*)(sm + AHI + p * 144 + ch * 16) = hval;
        if (TERMS == 2) {
            uint4 lval = v ? lv[gi] : z;
            *(uint4*)(sm + AHI + asz + p * 144 + ch * 16) = lval;
        }
    }
}

// 512-thread tap prefetch: each thread 2 x 16B
__device__ __forceinline__ void prefB512(char* sm, uint32_t boff, int slot,
        const fp16* w, int tap, int ncol, int tid) {
    char* dh = sm + boff + slot * 18432;
    const char* g = (const char*)w + (size_t)tap * 32768 + (size_t)ncol * 16384;
    #pragma unroll
    for (int jj = 0; jj < 2; jj++) {
        int j = tid * 2 + jj;
        int row = j >> 3, of = (j & 7) * 16;
        cpa16(smem_u32(dh + row * 144 + of), g + row * 128 + of);
    }
    cp_commit();
}

__device__ __forceinline__ void prefB_all(char* sm, const fp16* w, int ncol, int tid) {
    const char* g = (const char*)w + (size_t)ncol * 16384;
    for (int i = tid; i < 9216; i += 512) {
        int tap = i >> 10, j = i & 1023;
        int row = j >> 3, of = (j & 7) * 16;
        cpa16(smem_u32(sm + LBOFF + tap * 18432 + row * 144 + of),
              g + (size_t)tap * 32768 + row * 128 + of);
    }
    cp_commit();
}

template<int MT, int NTP>
__device__ __forceinline__ void mk_addrs(uint32_t smb, uint32_t asz, int warp_m,
        int warp_n, int l, uint32_t aH[][3], uint32_t aL[][3], uint32_t* bOf) {
    #pragma unroll
    for (int mt = 0; mt < MT; mt++) {
        int prow16 = warp_m * MT + mt;
        #pragma unroll
        for (int kw = 0; kw < 3; kw++) {
            int col = (l & 15) + kw - 1;
            uint32_t kpart = (uint32_t)(l >> 4) * 16;
            if ((unsigned)col > 15u) { aH[mt][kw] = smb + kpart; aL[mt][kw] = smb + kpart; }
            else {
                uint32_t base = smb + AHI + (uint32_t)(prow16 * 16 + col) * 144 + kpart;
                aH[mt][kw] = base;
                aL[mt][kw] = base + asz;
            }
        }
    }
    #pragma unroll
    for (int ntp = 0; ntp < NTP; ntp++) {
        int nl = warp_n * (NTP * 16) + ntp * 16 + (l & 7) + ((l >> 4) << 3);
        bOf[ntp] = (uint32_t)nl * 144 + ((l >> 3) & 1) * 16;
    }
}

template<int MT, int NTP, int TERMS, int KC>
__device__ __forceinline__ void gemm_tap(float (*acc)[4],
        const uint32_t aH[][3], const uint32_t aL[][3], const uint32_t* bOf,
        uint32_t bbase, uint32_t akk, int kw) {
    #pragma unroll
    for (int kc = 0; kc < KC; kc++) {
        uint32_t ko = akk + (uint32_t)kc * 32;
        uint32_t ah[MT][4], al[MT][4], bh[NTP][4];
        #pragma unroll
        for (int mt = 0; mt < MT; mt++) {
            ldsm4(ah[mt], aH[mt][kw] + ko);
            if (TERMS == 2) ldsm4(al[mt], aL[mt][kw] + ko);
        }
        #pragma unroll
        for (int ntp = 0; ntp < NTP; ntp++)
            ldsm4(bh[ntp], bbase + bOf[ntp] + (uint32_t)kc * 32);
        #pragma unroll
        for (int mt = 0; mt < MT; mt++)
        #pragma unroll
        for (int ntp = 0; ntp < NTP; ntp++) {
            float* c0 = acc[(mt * NTP + ntp) * 2];
            float* c1 = acc[(mt * NTP + ntp) * 2 + 1];
            mma16816(c0, ah[mt], bh[ntp]);  mma16816(c1, ah[mt], bh[ntp] + 2);
            if (TERMS == 2) {
                mma16816(c0, al[mt], bh[ntp]);  mma16816(c1, al[mt], bh[ntp] + 2);
            }
        }
    }
}

__global__ void embed_kernel(const float* __restrict__ x) {
    int idx = blockIdx.x * 256 + threadIdx.x;
    if (idx >= NIMG * 256 * 64) return;
    int c = idx & 63, px = (idx >> 6) & 255, img = idx >> 14;
    int b = img / 28, t = img % 28;
    float v = 0.f;
    if (c < 24) {
        int flat = t * 24 + c;
        v = x[((size_t)(b * 112 + flat / 6) * 256 + px) * 6 + flat % 6];
    }
    g_xeh[idx] = __float2half(v);
}

__global__ void wprep_all(
    const float* __restrict__ wx0f, const float* __restrict__ wx0b,
    const float* __restrict__ wh0f, const float* __restrict__ wh0b,
    const float* __restrict__ wx1f, const float* __restrict__ wx1b,
    const float* __restrict__ wh1f, const float* __restrict__ wh1b) {
    int idx = blockIdx.x * 256 + threadIdx.x;
    if (idx < 524288) g_cst[idx] = 0.f;
    if (idx < 16384)  g_zeroh[idx] = __float2half(0.f);
    if (idx < 1024)   g_grpbar[idx] = 0u;
    if (idx >= 90 * TAPSZ) return;
    int ic = idx & 63, n = (idx >> 6) & 255, unit = idx >> 14;
    const float* w; int IC, u0;
    if (unit < 18)      { w = unit < 9  ? wx0f : wx0b; IC = 24;  u0 = unit < 9  ? 0  : 9;  }
    else if (unit < 36) { w = unit < 27 ? wh0f : wh0b; IC = 64;  u0 = unit < 27 ? 18 : 27; }
    else if (unit < 72) { w = unit < 54 ? wx1f : wx1b; IC = 128; u0 = unit < 54 ? 36 : 54; }
    else                { w = unit < 81 ? wh1f : wh1b; IC = 64;  u0 = unit < 81 ? 72 : 81; }
    int tl = unit - u0;
    int src = tl / 9, rtap = tl % 9, ics = src * 64 + ic;
    int f = n >> 2, g = n & 3;
    float v = (ics < IC) ? w[((size_t)rtap * IC + ics) * 256 + (g * 64 + f)] : 0.f;
    g_w[idx] = __float2half(v);
}

__global__ void zero_states() {
    int idx = blockIdx.x * 256 + threadIdx.x;
    if (idx < 524288) g_cst[idx] = 0.f;
    if (idx < 1024)   g_grpbar[idx] = 0u;
}

// 512-thread conv: 16 warps (4 m-groups x 4 n-groups), warp = M64 x N32
template<int NSRC, int KC>
__global__ void __launch_bounds__(512, 1) conv_mma_kernel(
    const fp16* __restrict__ s0h, const fp16* __restrict__ s1h,
    const fp16* __restrict__ wf, const fp16* __restrict__ wb,
    const float* __restrict__ bf_, const float* __restrict__ bb_) {
    extern __shared__ char sm[];
    uint32_t smb = smem_u32(sm);
    int tid = threadIdx.x, l = tid & 31, w = tid >> 5;
    int warp_m = w >> 2, warp_n = w & 3, q = l & 3;
    int img = blockIdx.x, dir = blockIdx.y, ncol = blockIdx.z;
    const fp16* wsel = dir ? wb : wf;
    const float* bias = dir ? bb_ : bf_;
    const int T = NSRC * 9;

    for (int i = tid; i < ZSZ / 16; i += 512)
        *(uint4*)(sm + i * 16) = make_uint4(0, 0, 0, 0);
    fill_A<1, 512>(sm, CASZ, s0h + (size_t)img * 16384, (const fp16*)0, 0, 18, tid);
    prefB512(sm, CBOFF, 0, wsel, 0, ncol, tid);
    prefB512(sm, CBOFF, 1, wsel, 1, ncol, tid);
    prefB512(sm, CBOFF, 2, wsel, 2, ncol, tid);

    uint32_t aH[4][3], aL[4][3], bOf[2];
    mk_addrs<4, 2>(smb, CASZ, warp_m, warp_n, l, aH, aL, bOf);
    float acc[16][4];
    #pragma unroll
    for (int i = 0; i < 16; i++)
        acc[i][0] = acc[i][1] = acc[i][2] = acc[i][3] = 0.f;

    int tap = 0;
    #pragma unroll 1
    for (int u = 0; u < NSRC; u++) {
        #pragma unroll 1
        for (int kh = 0; kh < 3; kh++) {
            uint32_t akk = (uint32_t)kh * 2304;
            #pragma unroll
            for (int kw = 0; kw < 3; kw++) {
                if (tap < T - 2) cp_wait2(); else if (tap == T - 2) cp_wait1(); else cp_wait0();
                __syncthreads();
                if (NSRC == 2 && tap == 9) {
                    fill_A<1, 512>(sm, CASZ, s1h + (size_t)img * 16384, (const fp16*)0, 0, 18, tid);
                    __syncthreads();
                }
                gemm_tap<4, 2, 1, KC>(acc, aH, aL, bOf,
                                      smb + CBOFF + (tap & 3) * 18432, akk, kw);
                __syncthreads();
                if (tap + 3 < T) prefB512(sm, CBOFF, (tap + 3) & 3, wsel, tap + 3, ncol, tid);
                tap++;
            }
        }
    }

    size_t xzo = (((size_t)dir * NIMG + img) * 2 + ncol) * 32768;
    #pragma unroll
    for (int mt = 0; mt < 4; mt++) {
        int m = warp_m * 64 + mt * 16 + (l >> 2);
        #pragma unroll
        for (int idx4 = 0; idx4 < 4; idx4++) {
            int ntp = idx4 >> 1, hh = idx4 & 1;
            float* c = acc[mt * 4 + ntp * 2 + hh];
            int nn = warp_n * 32 + ntp * 16 + hh * 8 + q * 2;
            int ng = ncol * 128 + nn;
            float b0 = __ldg(&bias[(ng & 3) * 64 + (ng >> 2)]);
            float b1 = __ldg(&bias[((ng + 1) & 3) * 64 + ((ng + 1) >> 2)]);
            int n4 = nn >> 2;
            int j = (q & 1) * 2;
            float* p0 = g_xz + xzo + (size_t)n4 * 1024 + m * 4 + j;
            *(float2*)p0 = make_float2(c[0] + b0, c[1] + b1);
            *(float2*)(p0 + 32) = make_float2(c[2] + b0, c[3] + b1);
        }
    }
}

// 512-thread persistent LSTM: 16 warps, each M=32 x N=32
__global__ void __launch_bounds__(512, 1) lstm_persist_kernel(
    const fp16* __restrict__ wf, const fp16* __restrict__ wb,
    fp16* __restrict__ q0h, fp16* __restrict__ q0l,
    fp16* __restrict__ q1h, fp16* __restrict__ q1l) {
    extern __shared__ char sm[];
    uint32_t smb = smem_u32(sm);
    int tid = threadIdx.x, l = tid & 31, w = tid >> 5;
    int warp_m = w >> 2, warp_n = w & 3, q = l & 3;
    int bx = blockIdx.x;
    int dir = bx >> 6, b = (bx >> 2) & 15, hf = (bx >> 1) & 1, ncol = bx & 1;
    const fp16* wsel = dir ? wb : wf;
    fp16* qh = dir ? q1h : q0h;
    fp16* ql = dir ? q1l : q0l;
    unsigned grp = (unsigned)(bx >> 2);

    prefB_all(sm, wsel, ncol, tid);
    for (int i = tid; i < ZSZ / 16; i += 512)
        *(uint4*)(sm + i * 16) = make_uint4(0, 0, 0, 0);

    uint32_t aH[2][3], aL[2][3], bOf[2];
    mk_addrs<2, 2>(smb, LASZ, warp_m, warp_n, l, aH, aL, bOf);
    size_t ctaBase = (size_t)bx * 4096;
    bool lower = !(l & 1);
    cp_wait0();
    __syncthreads();

    #pragma unroll 1
    for (int s = 0; s < 28; s++) {
        int t = dir ? (27 - s) : s;
        int img = b * 28 + t;
        int tprev = dir ? (t + 1) : (t - 1);
        const fp16* hs_ = (s == 0) ? g_zeroh : qh + (size_t)(b * 28 + tprev) * 16384;
        const fp16* ls_ = (s == 0) ? g_zeroh : ql + (size_t)(b * 28 + tprev) * 16384;

        fill_A<2, 512>(sm, LASZ, hs_, ls_, hf * 8, 10, tid);
        __syncthreads();

        // L1 prefetch of this step's xz gate values (consumed in the epilogue)
        size_t xzo = (((size_t)dir * NIMG + img) * 2 + ncol) * 32768;
        #pragma unroll
        for (int mt = 0; mt < 2; mt++) {
            int mbase2 = warp_m * 32 + mt * 16 + (l >> 2);
            int m2 = lower ? mbase2 : (mbase2 + 8);
            int pxg2 = hf * 128 + m2;
            #pragma unroll
            for (int nt = 0; nt < 4; nt++) {
                int n4p = warp_n * 8 + nt * 2 + (q >> 1);
                pref_l1(g_xz + xzo + (size_t)n4p * 1024 + pxg2 * 4);
            }
        }

        float acc[8][4];
        #pragma unroll
        for (int i = 0; i < 8; i++)
            acc[i][0] = acc[i][1] = acc[i][2] = acc[i][3] = 0.f;
        #pragma unroll 1
        for (int kh = 0; kh < 3; kh++) {
            uint32_t akk = (uint32_t)kh * 2304;
            uint32_t bb = smb + LBOFF + (uint32_t)kh * 3 * 18432;
            #pragma unroll
            for (int kw = 0; kw < 3; kw++)
                gemm_tap<2, 2, 2, 4>(acc, aH, aL, bOf, bb + (uint32_t)kw * 18432, akk, kw);
        }
        __syncthreads();

        #pragma unroll
        for (int mt = 0; mt < 2; mt++) {
            int mbase = warp_m * 32 + mt * 16 + (l >> 2);
            #pragma unroll
            for (int nt = 0; nt < 4; nt++) {
                float* c = acc[mt * 4 + nt];
                float o0 = __shfl_xor_sync(0xffffffffu, c[0], 1);
                float o1 = __shfl_xor_sync(0xffffffffu, c[1], 1);
                float o2 = __shfl_xor_sync(0xffffffffu, c[2], 1);
                float o3 = __shfl_xor_sync(0xffffffffu, c[3], 1);
                float iv, fv, gv, ov;
                int m;
                if (lower) { iv = c[0]; fv = c[1]; gv = o0;  ov = o1;  m = mbase; }
                else       { iv = o2;  fv = o3;  gv = c[2]; ov = c[3]; m = mbase + 8; }
                int chp = q >> 1;
                int n4 = warp_n * 8 + nt * 2 + chp;
                int pxg = hf * 128 + m;
                float4 z = *(const float4*)(g_xz + xzo + (size_t)n4 * 1024 + pxg * 4);
                iv = sigm(iv + z.x); fv = sigm(fv + z.y);
                gv = tanhf(gv + z.z); ov = sigm(ov + z.w);
                float* cs = g_cst + ctaBase + w * 256 + (mt * 4 + nt) * 32 + l;
                float cc = fv * (*cs) + iv * gv;
                *cs = cc;
                float hv = ov * tanhf(cc);
                fp16 hb = __float2half(hv);
                float lr = hv - __half2float(hb);
                int chc = warp_n * 8 + nt * 2 + chp;
                *(fp16*)(sm + AHI + m * 64 + chc * 2) = hb;
                *(fp16*)(sm + AHI + 8192 + m * 64 + chc * 2) = __float2half(lr);
            }
        }
        __syncthreads();

        {
            int px = tid >> 2, part = tid & 3;
            uint4 h0 = *(const uint4*)(sm + AHI + px * 64 + part * 16);
            uint4 l0 = *(const uint4*)(sm + AHI + 8192 + px * 64 + part * 16);
            size_t qidx = ((size_t)img * 256 + hf * 128 + px) * 64 + ncol * 32 + part * 8;
            *(uint4*)(qh + qidx) = h0;
            *(uint4*)(ql + qidx) = l0;
        }

        if (s < 27) {
            __syncthreads();
            if (tid == 0) {
                __threadfence();
                atomicAdd(&g_grpbar[grp * 32], 1u);
                unsigned target = 4u * (unsigned)(s + 1);
                volatile unsigned* bc = &g_grpbar[grp * 32];
                while (*bc < target) __nanosleep(32);
                __threadfence();
            }
            __syncthreads();
        }
    }
}

__global__ void __launch_bounds__(256) out_conv_kernel(
    const fp16* __restrict__ d0h, const fp16* __restrict__ d0l,
    const fp16* __restrict__ d1h, const fp16* __restrict__ d1l,
    const float* __restrict__ wout, const float* __restrict__ bout,
    float* __restrict__ out) {
    __shared__ float sh[3 * 16 * 128];
    __shared__ float ps[256];
    int n = blockIdx.x / 16, h = blockIdx.x % 16, tid = threadIdx.x;
    for (int i = tid; i < 3 * 16 * 128; i += 256) {
        int r = i / 2048, rem = i - r * 2048, c = rem >> 7, ch = rem & 127;
        int row = h - 1 + r;
        float v = 0.f;
        if (row >= 0 && row < 16) {
            size_t idx = ((size_t)n * 256 + row * 16 + c) * 64 + (ch & 63);
            if (ch < 64) v = __half2float(d0h[idx]) + __half2float(d0l[idx]);
            else         v = __half2float(d1h[idx]) + __half2float(d1l[idx]);
        }
        sh[i] = v;
    }
    __syncthreads();
    int p = tid >> 4, qq = tid & 15;
    float partial = 0.f;
    for (int kh = 0; kh < 3; kh++)
        for (int kw = 0; kw < 3; kw++) {
            int iw = p + kw - 1;
            if (iw < 0 || iw >= 16) continue;
            #pragma unroll
            for (int j = 0; j < 8; j++) {
                int ic = qq * 8 + j;
                partial += sh[(kh * 16 + iw) * 128 + ic] * wout[(kh * 3 + kw) * 128 + ic];
            }
        }
    ps[tid] = partial;
    __syncthreads();
    if (qq == 0) {
        float sum = bout[0];
        #pragma unroll
        for (int j = 0; j < 16; j++) sum += ps[p * 16 + j];
        out[((size_t)n * 16 + h) * 16 + p] = sum;
    }
}

extern "C" void kernel_launch(void* const* d_in, const int* in_sizes, int n_in,
                              void* d_out, int out_size) {
    const float* x    = (const float*)d_in[0];
    const float* wx0f = (const float*)d_in[1];
    const float* wh0f = (const float*)d_in[2];
    const float* b0f  = (const float*)d_in[3];
    const float* wx0b = (const float*)d_in[4];
    const float* wh0b = (const float*)d_in[5];
    const float* b0b  = (const float*)d_in[6];
    const float* wx1f = (const float*)d_in[7];
    const float* wh1f = (const float*)d_in[8];
    const float* b1f  = (const float*)d_in[9];
    const float* wx1b = (const float*)d_in[10];
    const float* wh1b = (const float*)d_in[11];
    const float* b1b  = (const float*)d_in[12];
    const float* wout = (const float*)d_in[13];
    const float* bout = (const float*)d_in[14];
    float* out = (float*)d_out;

    cudaFuncSetAttribute((const void*)conv_mma_kernel<1,2>, cudaFuncAttributeMaxDynamicSharedMemorySize, CSMEM);
    cudaFuncSetAttribute((const void*)conv_mma_kernel<2,4>, cudaFuncAttributeMaxDynamicSharedMemorySize, CSMEM);
    cudaFuncSetAttribute((const void*)lstm_persist_kernel, cudaFuncAttributeMaxDynamicSharedMemorySize, LSMEM);

    fp16 *wg, *xeh, *q0h, *q0l, *q1h, *q1l;
    cudaGetSymbolAddress((void**)&wg, g_w);
    cudaGetSymbolAddress((void**)&xeh, g_xeh);
    cudaGetSymbolAddress((void**)&q0h, g_q0h);
    cudaGetSymbolAddress((void**)&q0l, g_q0l);
    cudaGetSymbolAddress((void**)&q1h, g_q1h);
    cudaGetSymbolAddress((void**)&q1l, g_q1l);

    wprep_all<<<(90*TAPSZ + 255)/256, 256>>>(wx0f, wx0b, wh0f, wh0b,
                                             wx1f, wx1b, wh1f, wh1b);          // 0
    embed_kernel<<<(NIMG*256*64 + 255)/256, 256>>>(x);                         // 1
    dim3 cgrid(NIMG, 2, 2);
    conv_mma_kernel<1,2><<<cgrid, 512, CSMEM>>>(xeh, xeh,
        wg + (size_t)0*TAPSZ, wg + (size_t)9*TAPSZ, b0f, b0b);                 // 2
    lstm_persist_kernel<<<128, 512, LSMEM>>>(
        wg + (size_t)18*TAPSZ, wg + (size_t)27*TAPSZ, q0h, q0l, q1h, q1l);     // 3 <- captured
    zero_states<<<2048, 256>>>();                                              // 4
    conv_mma_kernel<2,4><<<cgrid, 512, CSMEM>>>(q0h, q1h,
        wg + (size_t)36*TAPSZ, wg + (size_t)54*TAPSZ, b1f, b1b);               // 5
    lstm_persist_kernel<<<128, 512, LSMEM>>>(
        wg + (size_t)72*TAPSZ, wg + (size_t)81*TAPSZ, q0h, q0l, q1h, q1l);     // 6
    out_conv_kernel<<<NIMG*16, 256>>>(q0h, q0l, q1h, q1l, wout, bout, out);    // 7
}

// round 16
// speedup vs baseline: 1.2592x; 1.0037x over previous
#include <cuda_runtime.h>
#include <cuda_fp16.h>
#include <stdint.h>
#include <math.h>

typedef __half fp16;

#define NIMG 448
#define TAPSZ 16384
#define ZSZ   4864
#define AHI   4864
#define LASZ  23040
#define LBOFF (AHI + 2*LASZ)           // 50944
#define LSMEM (LBOFF + 9*18432)        // 216832
#define CASZ  41472
#define CBOFF (AHI + CASZ)             // 46336
#define CSMEM (CBOFF + 4*18432)        // 120064

__device__ fp16  g_xeh[(size_t)NIMG*256*64];
__device__ float g_xz[(size_t)2*NIMG*2*32768];   // [dir][img][ncol][n4(32)][px(256)][4]
__device__ fp16  g_q0h[(size_t)NIMG*256*64], g_q0l[(size_t)NIMG*256*64];
__device__ fp16  g_q1h[(size_t)NIMG*256*64], g_q1l[(size_t)NIMG*256*64];
__device__ float g_cst[524288];
__device__ fp16  g_w[(size_t)90*TAPSZ];
__device__ fp16  g_zeroh[16384];
__device__ unsigned g_grpbar[1024];

__device__ __forceinline__ uint32_t smem_u32(const void* p) {
    uint32_t a;
    asm("{ .reg .u64 t; cvta.to.shared.u64 t, %1; cvt.u32.u64 %0, t; }" : "=r"(a) : "l"(p));
    return a;
}
__device__ __forceinline__ void ldsm4(uint32_t* r, uint32_t addr) {
    asm volatile("ldmatrix.sync.aligned.m8n8.x4.shared.b16 {%0,%1,%2,%3}, [%4];"
        : "=r"(r[0]), "=r"(r[1]), "=r"(r[2]), "=r"(r[3]) : "r"(addr));
}
__device__ __forceinline__ void mma16816(float* c, const uint32_t* a, const uint32_t* b) {
    asm volatile("mma.sync.aligned.m16n8k16.row.col.f32.f16.f16.f32 "
        "{%0,%1,%2,%3}, {%4,%5,%6,%7}, {%8,%9}, {%0,%1,%2,%3};"
        : "+f"(c[0]), "+f"(c[1]), "+f"(c[2]), "+f"(c[3])
        : "r"(a[0]), "r"(a[1]), "r"(a[2]), "r"(a[3]), "r"(b[0]), "r"(b[1]));
}
__device__ __forceinline__ void cpa16(uint32_t dst, const void* src) {
    asm volatile("cp.async.cg.shared.global [%0], [%1], 16;" :: "r"(dst), "l"(src) : "memory");
}
__device__ __forceinline__ void cpa16z(uint32_t dst, const void* src, int sz) {
    asm volatile("cp.async.cg.shared.global [%0], [%1], 16, %2;"
        :: "r"(dst), "l"(src), "r"(sz) : "memory");
}
__device__ __forceinline__ void cp_commit() { asm volatile("cp.async.commit_group;" ::: "memory"); }
__device__ __forceinline__ void cp_wait2()  { asm volatile("cp.async.wait_group 2;" ::: "memory"); }
__device__ __forceinline__ void cp_wait1()  { asm volatile("cp.async.wait_group 1;" ::: "memory"); }
__device__ __forceinline__ void cp_wait0()  { asm volatile("cp.async.wait_group 0;" ::: "memory"); }
__device__ __forceinline__ void pref_l1(const void* p) {
    asm volatile("prefetch.global.L1 [%0];" :: "l"(p));
}
__device__ __forceinline__ float sigm(float x) { return __fdividef(1.f, 1.f + __expf(-x)); }
__device__ __forceinline__ float tanh_fast(float x) {
    float xc = fminf(fmaxf(x, -9.f), 9.f);
    float e = __expf(2.f * xc);
    return __fdividef(e - 1.f, e + 1.f);
}

// register-path fill (used by conv; mid-loop call can't mix with cp.async ring)
template<int TERMS, int NTHR>
__device__ __forceinline__ void fill_A(char* sm, uint32_t asz,
        const fp16* hsrc, const fp16* lsrc, int r0, int nrows, int tid) {
    const uint4* hv = (const uint4*)hsrc;
    const uint4* lv = (const uint4*)lsrc;
    const uint4 z = make_uint4(0, 0, 0, 0);
    int tot = nrows * 16 * 8;
    for (int i = tid; i < tot; i += NTHR) {
        int ch = i & 7, p = i >> 3;
        int hr = p >> 4, c = p & 15;
        int row = r0 - 1 + hr;
        bool v = (row >= 0 && row < 16);
        int gi = (row * 16 + c) * 8 + ch;
        uint4 hval = v ? hv[gi] : z;
        *(uint4*)(sm + AHI + p * 144 + ch * 16) = hval;
        if (TERMS == 2) {
            uint4 lval = v ? lv[gi] : z;
            *(uint4*)(sm + AHI + asz + p * 144 + ch * 16) = lval;
        }
    }
}

// async fill (LSTM): zfill for halo rows; caller commits + waits
__device__ __forceinline__ void fill_A_async(char* sm, uint32_t asz,
        const fp16* hsrc, const fp16* lsrc, int r0, int tid) {
    const uint4* hv = (const uint4*)hsrc;
    const uint4* lv = (const uint4*)lsrc;
    for (int i = tid; i < 10 * 16 * 8; i += 512) {
        int ch = i & 7, p = i >> 3;
        int hr = p >> 4, c = p & 15;
        int row = r0 - 1 + hr;
        bool v = (row >= 0 && row < 16);
        int sz = v ? 16 : 0;
        int gi = v ? ((row * 16 + c) * 8 + ch) : 0;
        uint32_t d = smem_u32(sm + AHI + p * 144 + ch * 16);
        cpa16z(d, hv + gi, sz);
        cpa16z(d + asz, lv + gi, sz);
    }
    cp_commit();
}

__device__ __forceinline__ void prefB512(char* sm, uint32_t boff, int slot,
        const fp16* w, int tap, int ncol, int tid) {
    char* dh = sm + boff + slot * 18432;
    const char* g = (const char*)w + (size_t)tap * 32768 + (size_t)ncol * 16384;
    #pragma unroll
    for (int jj = 0; jj < 2; jj++) {
        int j = tid * 2 + jj;
        int row = j >> 3, of = (j & 7) * 16;
        cpa16(smem_u32(dh + row * 144 + of), g + row * 128 + of);
    }
    cp_commit();
}

__device__ __forceinline__ void prefB_all(char* sm, const fp16* w, int ncol, int tid) {
    const char* g = (const char*)w + (size_t)ncol * 16384;
    for (int i = tid; i < 9216; i += 512) {
        int tap = i >> 10, j = i & 1023;
        int row = j >> 3, of = (j & 7) * 16;
        cpa16(smem_u32(sm + LBOFF + tap * 18432 + row * 144 + of),
              g + (size_t)tap * 32768 + row * 128 + of);
    }
    cp_commit();
}

template<int MT, int NTP>
__device__ __forceinline__ void mk_addrs(uint32_t smb, uint32_t asz, int warp_m,
        int warp_n, int l, uint32_t aH[][3], uint32_t aL[][3], uint32_t* bOf) {
    #pragma unroll
    for (int mt = 0; mt < MT; mt++) {
        int prow16 = warp_m * MT + mt;
        #pragma unroll
        for (int kw = 0; kw < 3; kw++) {
            int col = (l & 15) + kw - 1;
            uint32_t kpart = (uint32_t)(l >> 4) * 16;
            if ((unsigned)col > 15u) { aH[mt][kw] = smb + kpart; aL[mt][kw] = smb + kpart; }
            else {
                uint32_t base = smb + AHI + (uint32_t)(prow16 * 16 + col) * 144 + kpart;
                aH[mt][kw] = base;
                aL[mt][kw] = base + asz;
            }
        }
    }
    #pragma unroll
    for (int ntp = 0; ntp < NTP; ntp++) {
        int nl = warp_n * (NTP * 16) + ntp * 16 + (l & 7) + ((l >> 4) << 3);
        bOf[ntp] = (uint32_t)nl * 144 + ((l >> 3) & 1) * 16;
    }
}

template<int MT, int NTP, int TERMS, int KC>
__device__ __forceinline__ void gemm_tap(float (*acc)[4],
        const uint32_t aH[][3], const uint32_t aL[][3], const uint32_t* bOf,
        uint32_t bbase, uint32_t akk, int kw) {
    #pragma unroll
    for (int kc = 0; kc < KC; kc++) {
        uint32_t ko = akk + (uint32_t)kc * 32;
        uint32_t ah[MT][4], al[MT][4], bh[NTP][4];
        #pragma unroll
        for (int mt = 0; mt < MT; mt++) {
            ldsm4(ah[mt], aH[mt][kw] + ko);
            if (TERMS == 2) ldsm4(al[mt], aL[mt][kw] + ko);
        }
        #pragma unroll
        for (int ntp = 0; ntp < NTP; ntp++)
            ldsm4(bh[ntp], bbase + bOf[ntp] + (uint32_t)kc * 32);
        #pragma unroll
        for (int mt = 0; mt < MT; mt++)
        #pragma unroll
        for (int ntp = 0; ntp < NTP; ntp++) {
            float* c0 = acc[(mt * NTP + ntp) * 2];
            float* c1 = acc[(mt * NTP + ntp) * 2 + 1];
            mma16816(c0, ah[mt], bh[ntp]);  mma16816(c1, ah[mt], bh[ntp] + 2);
            if (TERMS == 2) {
                mma16816(c0, al[mt], bh[ntp]);  mma16816(c1, al[mt], bh[ntp] + 2);
            }
        }
    }
}

__global__ void embed_kernel(const float* __restrict__ x) {
    int idx = blockIdx.x * 256 + threadIdx.x;
    if (idx >= NIMG * 256 * 64) return;
    int c = idx & 63, px = (idx >> 6) & 255, img = idx >> 14;
    int b = img / 28, t = img % 28;
    float v = 0.f;
    if (c < 24) {
        int flat = t * 24 + c;
        v = x[((size_t)(b * 112 + flat / 6) * 256 + px) * 6 + flat % 6];
    }
    g_xeh[idx] = __float2half(v);
}

__global__ void wprep_all(
    const float* __restrict__ wx0f, const float* __restrict__ wx0b,
    const float* __restrict__ wh0f, const float* __restrict__ wh0b,
    const float* __restrict__ wx1f, const float* __restrict__ wx1b,
    const float* __restrict__ wh1f, const float* __restrict__ wh1b) {
    int idx = blockIdx.x * 256 + threadIdx.x;
    if (idx < 524288) g_cst[idx] = 0.f;
    if (idx < 16384)  g_zeroh[idx] = __float2half(0.f);
    if (idx < 1024)   g_grpbar[idx] = 0u;
    if (idx >= 90 * TAPSZ) return;
    int ic = idx & 63, n = (idx >> 6) & 255, unit = idx >> 14;
    const float* w; int IC, u0;
    if (unit < 18)      { w = unit < 9  ? wx0f : wx0b; IC = 24;  u0 = unit < 9  ? 0  : 9;  }
    else if (unit < 36) { w = unit < 27 ? wh0f : wh0b; IC = 64;  u0 = unit < 27 ? 18 : 27; }
    else if (unit < 72) { w = unit < 54 ? wx1f : wx1b; IC = 128; u0 = unit < 54 ? 36 : 54; }
    else                { w = unit < 81 ? wh1f : wh1b; IC = 64;  u0 = unit < 81 ? 72 : 81; }
    int tl = unit - u0;
    int src = tl / 9, rtap = tl % 9, ics = src * 64 + ic;
    int f = n >> 2, g = n & 3;
    float v = (ics < IC) ? w[((size_t)rtap * IC + ics) * 256 + (g * 64 + f)] : 0.f;
    g_w[idx] = __float2half(v);
}

__global__ void zero_states() {
    int idx = blockIdx.x * 256 + threadIdx.x;
    if (idx < 524288) g_cst[idx] = 0.f;
    if (idx < 1024)   g_grpbar[idx] = 0u;
}

template<int NSRC, int KC>
__global__ void __launch_bounds__(512, 1) conv_mma_kernel(
    const fp16* __restrict__ s0h, const fp16* __restrict__ s1h,
    const fp16* __restrict__ wf, const fp16* __restrict__ wb,
    const float* __restrict__ bf_, const float* __restrict__ bb_) {
    extern __shared__ char sm[];
    uint32_t smb = smem_u32(sm);
    int tid = threadIdx.x, l = tid & 31, w = tid >> 5;
    int warp_m = w >> 2, warp_n = w & 3, q = l & 3;
    int img = blockIdx.x, dir = blockIdx.y, ncol = blockIdx.z;
    const fp16* wsel = dir ? wb : wf;
    const float* bias = dir ? bb_ : bf_;
    const int T = NSRC * 9;

    for (int i = tid; i < ZSZ / 16; i += 512)
        *(uint4*)(sm + i * 16) = make_uint4(0, 0, 0, 0);
    fill_A<1, 512>(sm, CASZ, s0h + (size_t)img * 16384, (const fp16*)0, 0, 18, tid);
    prefB512(sm, CBOFF, 0, wsel, 0, ncol, tid);
    prefB512(sm, CBOFF, 1, wsel, 1, ncol, tid);
    prefB512(sm, CBOFF, 2, wsel, 2, ncol, tid);

    uint32_t aH[4][3], aL[4][3], bOf[2];
    mk_addrs<4, 2>(smb, CASZ, warp_m, warp_n, l, aH, aL, bOf);
    float acc[16][4];
    #pragma unroll
    for (int i = 0; i < 16; i++)
        acc[i][0] = acc[i][1] = acc[i][2] = acc[i][3] = 0.f;

    int tap = 0;
    #pragma unroll 1
    for (int u = 0; u < NSRC; u++) {
        #pragma unroll 1
        for (int kh = 0; kh < 3; kh++) {
            uint32_t akk = (uint32_t)kh * 2304;
            #pragma unroll
            for (int kw = 0; kw < 3; kw++) {
                if (tap < T - 2) cp_wait2(); else if (tap == T - 2) cp_wait1(); else cp_wait0();
                __syncthreads();
                if (NSRC == 2 && tap == 9) {
                    fill_A<1, 512>(sm, CASZ, s1h + (size_t)img * 16384, (const fp16*)0, 0, 18, tid);
                    __syncthreads();
                }
                gemm_tap<4, 2, 1, KC>(acc, aH, aL, bOf,
                                      smb + CBOFF + (tap & 3) * 18432, akk, kw);
                __syncthreads();
                if (tap + 3 < T) prefB512(sm, CBOFF, (tap + 3) & 3, wsel, tap + 3, ncol, tid);
                tap++;
            }
        }
    }

    size_t xzo = (((size_t)dir * NIMG + img) * 2 + ncol) * 32768;
    #pragma unroll
    for (int mt = 0; mt < 4; mt++) {
        int m = warp_m * 64 + mt * 16 + (l >> 2);
        #pragma unroll
        for (int idx4 = 0; idx4 < 4; idx4++) {
            int ntp = idx4 >> 1, hh = idx4 & 1;
            float* c = acc[mt * 4 + ntp * 2 + hh];
            int nn = warp_n * 32 + ntp * 16 + hh * 8 + q * 2;
            int ng = ncol * 128 + nn;
            float b0 = __ldg(&bias[(ng & 3) * 64 + (ng >> 2)]);
            float b1 = __ldg(&bias[((ng + 1) & 3) * 64 + ((ng + 1) >> 2)]);
            int n4 = nn >> 2;
            int j = (q & 1) * 2;
            float* p0 = g_xz + xzo + (size_t)n4 * 1024 + m * 4 + j;
            *(float2*)p0 = make_float2(c[0] + b0, c[1] + b1);
            *(float2*)(p0 + 32) = make_float2(c[2] + b0, c[3] + b1);
        }
    }
}

__global__ void __launch_bounds__(512, 1) lstm_persist_kernel(
    const fp16* __restrict__ wf, const fp16* __restrict__ wb,
    fp16* __restrict__ q0h, fp16* __restrict__ q0l,
    fp16* __restrict__ q1h, fp16* __restrict__ q1l) {
    extern __shared__ char sm[];
    uint32_t smb = smem_u32(sm);
    int tid = threadIdx.x, l = tid & 31, w = tid >> 5;
    int warp_m = w >> 2, warp_n = w & 3, q = l & 3;
    int bx = blockIdx.x;
    int dir = bx >> 6, b = (bx >> 2) & 15, hf = (bx >> 1) & 1, ncol = bx & 1;
    const fp16* wsel = dir ? wb : wf;
    fp16* qh = dir ? q1h : q0h;
    fp16* ql = dir ? q1l : q0l;
    unsigned grp = (unsigned)(bx >> 2);

    prefB_all(sm, wsel, ncol, tid);
    for (int i = tid; i < ZSZ / 16; i += 512)
        *(uint4*)(sm + i * 16) = make_uint4(0, 0, 0, 0);

    uint32_t aH[2][3], aL[2][3], bOf[2];
    mk_addrs<2, 2>(smb, LASZ, warp_m, warp_n, l, aH, aL, bOf);
    size_t ctaBase = (size_t)bx * 4096;
    bool lower = !(l & 1);
    cp_wait0();
    __syncthreads();

    #pragma unroll 1
    for (int s = 0; s < 28; s++) {
        int t = dir ? (27 - s) : s;
        int img = b * 28 + t;
        int tprev = dir ? (t + 1) : (t - 1);
        const fp16* hs_ = (s == 0) ? g_zeroh : qh + (size_t)(b * 28 + tprev) * 16384;
        const fp16* ls_ = (s == 0) ? g_zeroh : ql + (size_t)(b * 28 + tprev) * 16384;

        fill_A_async(sm, LASZ, hs_, ls_, hf * 8, tid);

        // L1 prefetch of this step's xz gate values (consumed in the epilogue)
        size_t xzo = (((size_t)dir * NIMG + img) * 2 + ncol) * 32768;
        #pragma unroll
        for (int mt = 0; mt < 2; mt++) {
            int mbase2 = warp_m * 32 + mt * 16 + (l >> 2);
            int m2 = lower ? mbase2 : (mbase2 + 8);
            int pxg2 = hf * 128 + m2;
            #pragma unroll
            for (int nt = 0; nt < 4; nt++) {
                int n4p = warp_n * 8 + nt * 2 + (q >> 1);
                pref_l1(g_xz + xzo + (size_t)n4p * 1024 + pxg2 * 4);
            }
        }
        cp_wait0();
        __syncthreads();

        float acc[8][4];
        #pragma unroll
        for (int i = 0; i < 8; i++)
            acc[i][0] = acc[i][1] = acc[i][2] = acc[i][3] = 0.f;
        #pragma unroll 1
        for (int kh = 0; kh < 3; kh++) {
            uint32_t akk = (uint32_t)kh * 2304;
            uint32_t bb = smb + LBOFF + (uint32_t)kh * 3 * 18432;
            #pragma unroll
            for (int kw = 0; kw < 3; kw++)
                gemm_tap<2, 2, 2, 4>(acc, aH, aL, bOf, bb + (uint32_t)kw * 18432, akk, kw);
        }
        __syncthreads();

        #pragma unroll
        for (int mt = 0; mt < 2; mt++) {
            int mbase = warp_m * 32 + mt * 16 + (l >> 2);
            #pragma unroll
            for (int nt = 0; nt < 4; nt++) {
                float* c = acc[mt * 4 + nt];
                float o0 = __shfl_xor_sync(0xffffffffu, c[0], 1);
                float o1 = __shfl_xor_sync(0xffffffffu, c[1], 1);
                float o2 = __shfl_xor_sync(0xffffffffu, c[2], 1);
                float o3 = __shfl_xor_sync(0xffffffffu, c[3], 1);
                float iv, fv, gv, ov;
                int m;
                if (lower) { iv = c[0]; fv = c[1]; gv = o0;  ov = o1;  m = mbase; }
                else       { iv = o2;  fv = o3;  gv = c[2]; ov = c[3]; m = mbase + 8; }
                int chp = q >> 1;
                int n4 = warp_n * 8 + nt * 2 + chp;
                int pxg = hf * 128 + m;
                float4 z = *(const float4*)(g_xz + xzo + (size_t)n4 * 1024 + pxg * 4);
                iv = sigm(iv + z.x); fv = sigm(fv + z.y);
                gv = tanh_fast(gv + z.z); ov = sigm(ov + z.w);
                float* cs = g_cst + ctaBase + w * 256 + (mt * 4 + nt) * 32 + l;
                float cc = fv * (*cs) + iv * gv;
                *cs = cc;
                float hv = ov * tanh_fast(cc);
                fp16 hb = __float2half(hv);
                float lr = hv - __half2float(hb);
                int chc = warp_n * 8 + nt * 2 + chp;
                *(fp16*)(sm + AHI + m * 64 + chc * 2) = hb;
                *(fp16*)(sm + AHI + 8192 + m * 64 + chc * 2) = __float2half(lr);
            }
        }
        __syncthreads();

        {
            int px = tid >> 2, part = tid & 3;
            uint4 h0 = *(const uint4*)(sm + AHI + px * 64 + part * 16);
            uint4 l0 = *(const uint4*)(sm + AHI + 8192 + px * 64 + part * 16);
            size_t qidx = ((size_t)img * 256 + hf * 128 + px) * 64 + ncol * 32 + part * 8;
            *(uint4*)(qh + qidx) = h0;
            *(uint4*)(ql + qidx) = l0;
        }

        if (s < 27) {
            __syncthreads();
            if (tid == 0) {
                __threadfence();
                atomicAdd(&g_grpbar[grp * 32], 1u);
                unsigned target = 4u * (unsigned)(s + 1);
                volatile unsigned* bc = &g_grpbar[grp * 32];
                while (*bc < target) __nanosleep(32);
                __threadfence();
            }
            __syncthreads();
        }
    }
}

__global__ void __launch_bounds__(256) out_conv_kernel(
    const fp16* __restrict__ d0h, const fp16* __restrict__ d0l,
    const fp16* __restrict__ d1h, const fp16* __restrict__ d1l,
    const float* __restrict__ wout, const float* __restrict__ bout,
    float* __restrict__ out) {
    __shared__ float sh[3 * 16 * 128];
    __shared__ float ps[256];
    int n = blockIdx.x / 16, h = blockIdx.x % 16, tid = threadIdx.x;
    for (int i = tid; i < 3 * 16 * 128; i += 256) {
        int r = i / 2048, rem = i - r * 2048, c = rem >> 7, ch = rem & 127;
        int row = h - 1 + r;
        float v = 0.f;
        if (row >= 0 && row < 16) {
            size_t idx = ((size_t)n * 256 + row * 16 + c) * 64 + (ch & 63);
            if (ch < 64) v = __half2float(d0h[idx]) + __half2float(d0l[idx]);
            else         v = __half2float(d1h[idx]) + __half2float(d1l[idx]);
        }
        sh[i] = v;
    }
    __syncthreads();
    int p = tid >> 4, qq = tid & 15;
    float partial = 0.f;
    for (int kh = 0; kh < 3; kh++)
        for (int kw = 0; kw < 3; kw++) {
            int iw = p + kw - 1;
            if (iw < 0 || iw >= 16) continue;
            #pragma unroll
            for (int j = 0; j < 8; j++) {
                int ic = qq * 8 + j;
                partial += sh[(kh * 16 + iw) * 128 + ic] * wout[(kh * 3 + kw) * 128 + ic];
            }
        }
    ps[tid] = partial;
    __syncthreads();
    if (qq == 0) {
        float sum = bout[0];
        #pragma unroll
        for (int j = 0; j < 16; j++) sum += ps[p * 16 + j];
        out[((size_t)n * 16 + h) * 16 + p] = sum;
    }
}

extern "C" void kernel_launch(void* const* d_in, const int* in_sizes, int n_in,
                              void* d_out, int out_size) {
    const float* x    = (const float*)d_in[0];
    const float* wx0f = (const float*)d_in[1];
    const float* wh0f = (const float*)d_in[2];
    const float* b0f  = (const float*)d_in[3];
    const float* wx0b = (const float*)d_in[4];
    const float* wh0b = (const float*)d_in[5];
    const float* b0b  = (const float*)d_in[6];
    const float* wx1f = (const float*)d_in[7];
    const float* wh1f = (const float*)d_in[8];
    const float* b1f  = (const float*)d_in[9];
    const float* wx1b = (const float*)d_in[10];
    const float* wh1b = (const float*)d_in[11];
    const float* b1b  = (const float*)d_in[12];
    const float* wout = (const float*)d_in[13];
    const float* bout = (const float*)d_in[14];
    float* out = (float*)d_out;

    cudaFuncSetAttribute((const void*)conv_mma_kernel<1,2>, cudaFuncAttributeMaxDynamicSharedMemorySize, CSMEM);
    cudaFuncSetAttribute((const void*)conv_mma_kernel<2,4>, cudaFuncAttributeMaxDynamicSharedMemorySize, CSMEM);
    cudaFuncSetAttribute((const void*)lstm_persist_kernel, cudaFuncAttributeMaxDynamicSharedMemorySize, LSMEM);

    fp16 *wg, *xeh, *q0h, *q0l, *q1h, *q1l;
    cudaGetSymbolAddress((void**)&wg, g_w);
    cudaGetSymbolAddress((void**)&xeh, g_xeh);
    cudaGetSymbolAddress((void**)&q0h, g_q0h);
    cudaGetSymbolAddress((void**)&q0l, g_q0l);
    cudaGetSymbolAddress((void**)&q1h, g_q1h);
    cudaGetSymbolAddress((void**)&q1l, g_q1l);

    wprep_all<<<(90*TAPSZ + 255)/256, 256>>>(wx0f, wx0b, wh0f, wh0b,
                                             wx1f, wx1b, wh1f, wh1b);          // 0
    embed_kernel<<<(NIMG*256*64 + 255)/256, 256>>>(x);                         // 1
    dim3 cgrid(NIMG, 2, 2);
    conv_mma_kernel<1,2><<<cgrid, 512, CSMEM>>>(xeh, xeh,
        wg + (size_t)0*TAPSZ, wg + (size_t)9*TAPSZ, b0f, b0b);                 // 2
    lstm_persist_kernel<<<128, 512, LSMEM>>>(
        wg + (size_t)18*TAPSZ, wg + (size_t)27*TAPSZ, q0h, q0l, q1h, q1l);     // 3 <- captured
    zero_states<<<2048, 256>>>();                                              // 4
    conv_mma_kernel<2,4><<<cgrid, 512, CSMEM>>>(q0h, q1h,
        wg + (size_t)36*TAPSZ, wg + (size_t)54*TAPSZ, b1f, b1b);               // 5
    lstm_persist_kernel<<<128, 512, LSMEM>>>(
        wg + (size_t)72*TAPSZ, wg + (size_t)81*TAPSZ, q0h, q0l, q1h, q1l);     // 6
    out_conv_kernel<<<NIMG*16, 256>>>(q0h, q0l, q1h, q1l, wout, bout, out);    // 7
}

// round 17
// speedup vs baseline: 1.3043x; 1.0358x over previous
#include <cuda_runtime.h>
#include <cuda_fp16.h>
#include <stdint.h>
#include <math.h>

typedef __half fp16;

#define NIMG 448
#define TAPSZ 16384
#define ZSZ   4864
#define AHI   4864
#define LASZ  23040
#define LBOFF (AHI + 2*LASZ)           // 50944
#define LSMEM (LBOFF + 9*18432)        // 216832
#define CASZ  41472
#define CBOFF (AHI + CASZ)             // 46336
#define CSMEM (CBOFF + 4*18432)        // 120064

__device__ fp16  g_xeh[(size_t)NIMG*256*64];
__device__ float g_xz[(size_t)2*NIMG*2*32768];   // [dir][img][ncol][n4(32)][px(256)][4]
__device__ fp16  g_q0h[(size_t)NIMG*256*64], g_q0l[(size_t)NIMG*256*64];
__device__ fp16  g_q1h[(size_t)NIMG*256*64], g_q1l[(size_t)NIMG*256*64];
__device__ float g_cst[524288];
__device__ fp16  g_w[(size_t)90*TAPSZ];
__device__ fp16  g_zeroh[16384];
__device__ unsigned g_grpbar[1024];

__device__ __forceinline__ uint32_t smem_u32(const void* p) {
    uint32_t a;
    asm("{ .reg .u64 t; cvta.to.shared.u64 t, %1; cvt.u32.u64 %0, t; }" : "=r"(a) : "l"(p));
    return a;
}
__device__ __forceinline__ void ldsm4(uint32_t* r, uint32_t addr) {
    asm volatile("ldmatrix.sync.aligned.m8n8.x4.shared.b16 {%0,%1,%2,%3}, [%4];"
        : "=r"(r[0]), "=r"(r[1]), "=r"(r[2]), "=r"(r[3]) : "r"(addr));
}
__device__ __forceinline__ void mma16816(float* c, const uint32_t* a, const uint32_t* b) {
    asm volatile("mma.sync.aligned.m16n8k16.row.col.f32.f16.f16.f32 "
        "{%0,%1,%2,%3}, {%4,%5,%6,%7}, {%8,%9}, {%0,%1,%2,%3};"
        : "+f"(c[0]), "+f"(c[1]), "+f"(c[2]), "+f"(c[3])
        : "r"(a[0]), "r"(a[1]), "r"(a[2]), "r"(a[3]), "r"(b[0]), "r"(b[1]));
}
__device__ __forceinline__ void cpa16(uint32_t dst, const void* src) {
    asm volatile("cp.async.cg.shared.global [%0], [%1], 16;" :: "r"(dst), "l"(src) : "memory");
}
__device__ __forceinline__ void cpa16z(uint32_t dst, const void* src, int sz) {
    asm volatile("cp.async.cg.shared.global [%0], [%1], 16, %2;"
        :: "r"(dst), "l"(src), "r"(sz) : "memory");
}
__device__ __forceinline__ void cp_commit() { asm volatile("cp.async.commit_group;" ::: "memory"); }
__device__ __forceinline__ void cp_wait2()  { asm volatile("cp.async.wait_group 2;" ::: "memory"); }
__device__ __forceinline__ void cp_wait1()  { asm volatile("cp.async.wait_group 1;" ::: "memory"); }
__device__ __forceinline__ void cp_wait0()  { asm volatile("cp.async.wait_group 0;" ::: "memory"); }
__device__ __forceinline__ void pref_l1(const void* p) {
    asm volatile("prefetch.global.L1 [%0];" :: "l"(p));
}
__device__ __forceinline__ void cluster_arrive() {
    asm volatile("barrier.cluster.arrive.aligned;" ::: "memory");
}
__device__ __forceinline__ void cluster_wait() {
    asm volatile("barrier.cluster.wait.aligned;" ::: "memory");
}
__device__ __forceinline__ float sigm(float x) { return __fdividef(1.f, 1.f + __expf(-x)); }
__device__ __forceinline__ float tanh_fast(float x) {
    float xc = fminf(fmaxf(x, -9.f), 9.f);
    float e = __expf(2.f * xc);
    return __fdividef(e - 1.f, e + 1.f);
}

template<int TERMS, int NTHR>
__device__ __forceinline__ void fill_A(char* sm, uint32_t asz,
        const fp16* hsrc, const fp16* lsrc, int r0, int nrows, int tid) {
    const uint4* hv = (const uint4*)hsrc;
    const uint4* lv = (const uint4*)lsrc;
    const uint4 z = make_uint4(0, 0, 0, 0);
    int tot = nrows * 16 * 8;
    for (int i = tid; i < tot; i += NTHR) {
        int ch = i & 7, p = i >> 3;
        int hr = p >> 4, c = p & 15;
        int row = r0 - 1 + hr;
        bool v = (row >= 0 && row < 16);
        int gi = (row * 16 + c) * 8 + ch;
        uint4 hval = v ? hv[gi] : z;
        *(uint4*)(sm + AHI + p * 144 + ch * 16) = hval;
        if (TERMS == 2) {
            uint4 lval = v ? lv[gi] : z;
            *(uint4*)(sm + AHI + asz + p * 144 + ch * 16) = lval;
        }
    }
}

__device__ __forceinline__ void fill_A_async(char* sm, uint32_t asz,
        const fp16* hsrc, const fp16* lsrc, int r0, int tid) {
    const uint4* hv = (const uint4*)hsrc;
    const uint4* lv = (const uint4*)lsrc;
    for (int i = tid; i < 10 * 16 * 8; i += 512) {
        int ch = i & 7, p = i >> 3;
        int hr = p >> 4, c = p & 15;
        int row = r0 - 1 + hr;
        bool v = (row >= 0 && row < 16);
        int sz = v ? 16 : 0;
        int gi = v ? ((row * 16 + c) * 8 + ch) : 0;
        uint32_t d = smem_u32(sm + AHI + p * 144 + ch * 16);
        cpa16z(d, hv + gi, sz);
        cpa16z(d + asz, lv + gi, sz);
    }
    cp_commit();
}

__device__ __forceinline__ void prefB512(char* sm, uint32_t boff, int slot,
        const fp16* w, int tap, int ncol, int tid) {
    char* dh = sm + boff + slot * 18432;
    const char* g = (const char*)w + (size_t)tap * 32768 + (size_t)ncol * 16384;
    #pragma unroll
    for (int jj = 0; jj < 2; jj++) {
        int j = tid * 2 + jj;
        int row = j >> 3, of = (j & 7) * 16;
        cpa16(smem_u32(dh + row * 144 + of), g + row * 128 + of);
    }
    cp_commit();
}

__device__ __forceinline__ void prefB_all(char* sm, const fp16* w, int ncol, int tid) {
    const char* g = (const char*)w + (size_t)ncol * 16384;
    for (int i = tid; i < 9216; i += 512) {
        int tap = i >> 10, j = i & 1023;
        int row = j >> 3, of = (j & 7) * 16;
        cpa16(smem_u32(sm + LBOFF + tap * 18432 + row * 144 + of),
              g + (size_t)tap * 32768 + row * 128 + of);
    }
    cp_commit();
}

template<int MT, int NTP>
__device__ __forceinline__ void mk_addrs(uint32_t smb, uint32_t asz, int warp_m,
        int warp_n, int l, uint32_t aH[][3], uint32_t aL[][3], uint32_t* bOf) {
    #pragma unroll
    for (int mt = 0; mt < MT; mt++) {
        int prow16 = warp_m * MT + mt;
        #pragma unroll
        for (int kw = 0; kw < 3; kw++) {
            int col = (l & 15) + kw - 1;
            uint32_t kpart = (uint32_t)(l >> 4) * 16;
            if ((unsigned)col > 15u) { aH[mt][kw] = smb + kpart; aL[mt][kw] = smb + kpart; }
            else {
                uint32_t base = smb + AHI + (uint32_t)(prow16 * 16 + col) * 144 + kpart;
                aH[mt][kw] = base;
                aL[mt][kw] = base + asz;
            }
        }
    }
    #pragma unroll
    for (int ntp = 0; ntp < NTP; ntp++) {
        int nl = warp_n * (NTP * 16) + ntp * 16 + (l & 7) + ((l >> 4) << 3);
        bOf[ntp] = (uint32_t)nl * 144 + ((l >> 3) & 1) * 16;
    }
}

template<int MT, int NTP, int TERMS, int KC>
__device__ __forceinline__ void gemm_tap(float (*acc)[4],
        const uint32_t aH[][3], const uint32_t aL[][3], const uint32_t* bOf,
        uint32_t bbase, uint32_t akk, int kw) {
    #pragma unroll
    for (int kc = 0; kc < KC; kc++) {
        uint32_t ko = akk + (uint32_t)kc * 32;
        uint32_t ah[MT][4], al[MT][4], bh[NTP][4];
        #pragma unroll
        for (int mt = 0; mt < MT; mt++) {
            ldsm4(ah[mt], aH[mt][kw] + ko);
            if (TERMS == 2) ldsm4(al[mt], aL[mt][kw] + ko);
        }
        #pragma unroll
        for (int ntp = 0; ntp < NTP; ntp++)
            ldsm4(bh[ntp], bbase + bOf[ntp] + (uint32_t)kc * 32);
        #pragma unroll
        for (int mt = 0; mt < MT; mt++)
        #pragma unroll
        for (int ntp = 0; ntp < NTP; ntp++) {
            float* c0 = acc[(mt * NTP + ntp) * 2];
            float* c1 = acc[(mt * NTP + ntp) * 2 + 1];
            mma16816(c0, ah[mt], bh[ntp]);  mma16816(c1, ah[mt], bh[ntp] + 2);
            if (TERMS == 2) {
                mma16816(c0, al[mt], bh[ntp]);  mma16816(c1, al[mt], bh[ntp] + 2);
            }
        }
    }
}

__global__ void embed_kernel(const float* __restrict__ x) {
    int idx = blockIdx.x * 256 + threadIdx.x;
    if (idx >= NIMG * 256 * 64) return;
    int c = idx & 63, px = (idx >> 6) & 255, img = idx >> 14;
    int b = img / 28, t = img % 28;
    float v = 0.f;
    if (c < 24) {
        int flat = t * 24 + c;
        v = x[((size_t)(b * 112 + flat / 6) * 256 + px) * 6 + flat % 6];
    }
    g_xeh[idx] = __float2half(v);
}

__global__ void wprep_all(
    const float* __restrict__ wx0f, const float* __restrict__ wx0b,
    const float* __restrict__ wh0f, const float* __restrict__ wh0b,
    const float* __restrict__ wx1f, const float* __restrict__ wx1b,
    const float* __restrict__ wh1f, const float* __restrict__ wh1b) {
    int idx = blockIdx.x * 256 + threadIdx.x;
    if (idx < 524288) g_cst[idx] = 0.f;
    if (idx < 16384)  g_zeroh[idx] = __float2half(0.f);
    if (idx < 1024)   g_grpbar[idx] = 0u;
    if (idx >= 90 * TAPSZ) return;
    int ic = idx & 63, n = (idx >> 6) & 255, unit = idx >> 14;
    const float* w; int IC, u0;
    if (unit < 18)      { w = unit < 9  ? wx0f : wx0b; IC = 24;  u0 = unit < 9  ? 0  : 9;  }
    else if (unit < 36) { w = unit < 27 ? wh0f : wh0b; IC = 64;  u0 = unit < 27 ? 18 : 27; }
    else if (unit < 72) { w = unit < 54 ? wx1f : wx1b; IC = 128; u0 = unit < 54 ? 36 : 54; }
    else                { w = unit < 81 ? wh1f : wh1b; IC = 64;  u0 = unit < 81 ? 72 : 81; }
    int tl = unit - u0;
    int src = tl / 9, rtap = tl % 9, ics = src * 64 + ic;
    int f = n >> 2, g = n & 3;
    float v = (ics < IC) ? w[((size_t)rtap * IC + ics) * 256 + (g * 64 + f)] : 0.f;
    g_w[idx] = __float2half(v);
}

__global__ void zero_states() {
    int idx = blockIdx.x * 256 + threadIdx.x;
    if (idx < 524288) g_cst[idx] = 0.f;
    if (idx < 1024)   g_grpbar[idx] = 0u;
}

template<int NSRC, int KC>
__global__ void __launch_bounds__(512, 1) conv_mma_kernel(
    const fp16* __restrict__ s0h, const fp16* __restrict__ s1h,
    const fp16* __restrict__ wf, const fp16* __restrict__ wb,
    const float* __restrict__ bf_, const float* __restrict__ bb_) {
    extern __shared__ char sm[];
    uint32_t smb = smem_u32(sm);
    int tid = threadIdx.x, l = tid & 31, w = tid >> 5;
    int warp_m = w >> 2, warp_n = w & 3, q = l & 3;
    int img = blockIdx.x, dir = blockIdx.y, ncol = blockIdx.z;
    const fp16* wsel = dir ? wb : wf;
    const float* bias = dir ? bb_ : bf_;
    const int T = NSRC * 9;

    for (int i = tid; i < ZSZ / 16; i += 512)
        *(uint4*)(sm + i * 16) = make_uint4(0, 0, 0, 0);
    fill_A<1, 512>(sm, CASZ, s0h + (size_t)img * 16384, (const fp16*)0, 0, 18, tid);
    prefB512(sm, CBOFF, 0, wsel, 0, ncol, tid);
    prefB512(sm, CBOFF, 1, wsel, 1, ncol, tid);
    prefB512(sm, CBOFF, 2, wsel, 2, ncol, tid);

    uint32_t aH[4][3], aL[4][3], bOf[2];
    mk_addrs<4, 2>(smb, CASZ, warp_m, warp_n, l, aH, aL, bOf);
    float acc[16][4];
    #pragma unroll
    for (int i = 0; i < 16; i++)
        acc[i][0] = acc[i][1] = acc[i][2] = acc[i][3] = 0.f;

    int tap = 0;
    #pragma unroll 1
    for (int u = 0; u < NSRC; u++) {
        #pragma unroll 1
        for (int kh = 0; kh < 3; kh++) {
            uint32_t akk = (uint32_t)kh * 2304;
            #pragma unroll
            for (int kw = 0; kw < 3; kw++) {
                if (tap < T - 2) cp_wait2(); else if (tap == T - 2) cp_wait1(); else cp_wait0();
                __syncthreads();
                if (NSRC == 2 && tap == 9) {
                    fill_A<1, 512>(sm, CASZ, s1h + (size_t)img * 16384, (const fp16*)0, 0, 18, tid);
                    __syncthreads();
                }
                // safe: all warps passed the sync => gemm(tap-1), the only reader of
                // slot (tap+3)&3 == (tap-1)&3, has completed on every warp.
                if (tap + 3 < T) prefB512(sm, CBOFF, (tap + 3) & 3, wsel, tap + 3, ncol, tid);
                gemm_tap<4, 2, 1, KC>(acc, aH, aL, bOf,
                                      smb + CBOFF + (tap & 3) * 18432, akk, kw);
                tap++;
            }
        }
    }

    size_t xzo = (((size_t)dir * NIMG + img) * 2 + ncol) * 32768;
    #pragma unroll
    for (int mt = 0; mt < 4; mt++) {
        int m = warp_m * 64 + mt * 16 + (l >> 2);
        #pragma unroll
        for (int idx4 = 0; idx4 < 4; idx4++) {
            int ntp = idx4 >> 1, hh = idx4 & 1;
            float* c = acc[mt * 4 + ntp * 2 + hh];
            int nn = warp_n * 32 + ntp * 16 + hh * 8 + q * 2;
            int ng = ncol * 128 + nn;
            float b0 = __ldg(&bias[(ng & 3) * 64 + (ng >> 2)]);
            float b1 = __ldg(&bias[((ng + 1) & 3) * 64 + ((ng + 1) >> 2)]);
            int n4 = nn >> 2;
            int j = (q & 1) * 2;
            float* p0 = g_xz + xzo + (size_t)n4 * 1024 + m * 4 + j;
            *(float2*)p0 = make_float2(c[0] + b0, c[1] + b1);
            *(float2*)(p0 + 32) = make_float2(c[2] + b0, c[3] + b1);
        }
    }
}

// persistent LSTM, launched as clusters of 4 CTAs (= one (dir,b) halo group)
__global__ void __launch_bounds__(512, 1) lstm_persist_kernel(
    const fp16* __restrict__ wf, const fp16* __restrict__ wb,
    fp16* __restrict__ q0h, fp16* __restrict__ q0l,
    fp16* __restrict__ q1h, fp16* __restrict__ q1l) {
    extern __shared__ char sm[];
    uint32_t smb = smem_u32(sm);
    int tid = threadIdx.x, l = tid & 31, w = tid >> 5;
    int warp_m = w >> 2, warp_n = w & 3, q = l & 3;
    int bx = blockIdx.x;
    int dir = bx >> 6, b = (bx >> 2) & 15, hf = (bx >> 1) & 1, ncol = bx & 1;
    const fp16* wsel = dir ? wb : wf;
    fp16* qh = dir ? q1h : q0h;
    fp16* ql = dir ? q1l : q0l;

    prefB_all(sm, wsel, ncol, tid);
    for (int i = tid; i < ZSZ / 16; i += 512)
        *(uint4*)(sm + i * 16) = make_uint4(0, 0, 0, 0);

    uint32_t aH[2][3], aL[2][3], bOf[2];
    mk_addrs<2, 2>(smb, LASZ, warp_m, warp_n, l, aH, aL, bOf);
    size_t ctaBase = (size_t)bx * 4096;
    bool lower = !(l & 1);
    cp_wait0();
    __syncthreads();

    #pragma unroll 1
    for (int s = 0; s < 28; s++) {
        int t = dir ? (27 - s) : s;
        int img = b * 28 + t;
        int tprev = dir ? (t + 1) : (t - 1);
        const fp16* hs_ = (s == 0) ? g_zeroh : qh + (size_t)(b * 28 + tprev) * 16384;
        const fp16* ls_ = (s == 0) ? g_zeroh : ql + (size_t)(b * 28 + tprev) * 16384;

        fill_A_async(sm, LASZ, hs_, ls_, hf * 8, tid);

        size_t xzo = (((size_t)dir * NIMG + img) * 2 + ncol) * 32768;
        #pragma unroll
        for (int mt = 0; mt < 2; mt++) {
            int mbase2 = warp_m * 32 + mt * 16 + (l >> 2);
            int m2 = lower ? mbase2 : (mbase2 + 8);
            int pxg2 = hf * 128 + m2;
            #pragma unroll
            for (int nt = 0; nt < 4; nt++) {
                int n4p = warp_n * 8 + nt * 2 + (q >> 1);
                pref_l1(g_xz + xzo + (size_t)n4p * 1024 + pxg2 * 4);
            }
        }
        cp_wait0();
        __syncthreads();

        float acc[8][4];
        #pragma unroll
        for (int i = 0; i < 8; i++)
            acc[i][0] = acc[i][1] = acc[i][2] = acc[i][3] = 0.f;
        #pragma unroll 1
        for (int kh = 0; kh < 3; kh++) {
            uint32_t akk = (uint32_t)kh * 2304;
            uint32_t bb = smb + LBOFF + (uint32_t)kh * 3 * 18432;
            #pragma unroll
            for (int kw = 0; kw < 3; kw++)
                gemm_tap<2, 2, 2, 4>(acc, aH, aL, bOf, bb + (uint32_t)kw * 18432, akk, kw);
        }
        __syncthreads();

        #pragma unroll
        for (int mt = 0; mt < 2; mt++) {
            int mbase = warp_m * 32 + mt * 16 + (l >> 2);
            #pragma unroll
            for (int nt = 0; nt < 4; nt++) {
                float* c = acc[mt * 4 + nt];
                float o0 = __shfl_xor_sync(0xffffffffu, c[0], 1);
                float o1 = __shfl_xor_sync(0xffffffffu, c[1], 1);
                float o2 = __shfl_xor_sync(0xffffffffu, c[2], 1);
                float o3 = __shfl_xor_sync(0xffffffffu, c[3], 1);
                float iv, fv, gv, ov;
                int m;
                if (lower) { iv = c[0]; fv = c[1]; gv = o0;  ov = o1;  m = mbase; }
                else       { iv = o2;  fv = o3;  gv = c[2]; ov = c[3]; m = mbase + 8; }
                int chp = q >> 1;
                int n4 = warp_n * 8 + nt * 2 + chp;
                int pxg = hf * 128 + m;
                float4 z = *(const float4*)(g_xz + xzo + (size_t)n4 * 1024 + pxg * 4);
                iv = sigm(iv + z.x); fv = sigm(fv + z.y);
                gv = tanh_fast(gv + z.z); ov = sigm(ov + z.w);
                float* cs = g_cst + ctaBase + w * 256 + (mt * 4 + nt) * 32 + l;
                float cc = fv * (*cs) + iv * gv;
                *cs = cc;
                float hv = ov * tanh_fast(cc);
                fp16 hb = __float2half(hv);
                float lr = hv - __half2float(hb);
                int chc = warp_n * 8 + nt * 2 + chp;
                *(fp16*)(sm + AHI + m * 64 + chc * 2) = hb;
                *(fp16*)(sm + AHI + 8192 + m * 64 + chc * 2) = __float2half(lr);
            }
        }
        __syncthreads();

        {
            int px = tid >> 2, part = tid & 3;
            uint4 h0 = *(const uint4*)(sm + AHI + px * 64 + part * 16);
            uint4 l0 = *(const uint4*)(sm + AHI + 8192 + px * 64 + part * 16);
            size_t qidx = ((size_t)img * 256 + hf * 128 + px) * 64 + ncol * 32 + part * 8;
            *(uint4*)(qh + qidx) = h0;
            *(uint4*)(ql + qidx) = l0;
        }

        // cluster barrier: release q writes, acquire peers' writes; also syncs the CTA
        if (s < 27) {
            cluster_arrive();
            cluster_wait();
        }
    }
}

__global__ void __launch_bounds__(256) out_conv_kernel(
    const fp16* __restrict__ d0h, const fp16* __restrict__ d0l,
    const fp16* __restrict__ d1h, const fp16* __restrict__ d1l,
    const float* __restrict__ wout, const float* __restrict__ bout,
    float* __restrict__ out) {
    __shared__ float sh[3 * 16 * 128];
    __shared__ float ps[256];
    int n = blockIdx.x / 16, h = blockIdx.x % 16, tid = threadIdx.x;
    for (int i = tid; i < 3 * 16 * 128; i += 256) {
        int r = i / 2048, rem = i - r * 2048, c = rem >> 7, ch = rem & 127;
        int row = h - 1 + r;
        float v = 0.f;
        if (row >= 0 && row < 16) {
            size_t idx = ((size_t)n * 256 + row * 16 + c) * 64 + (ch & 63);
            if (ch < 64) v = __half2float(d0h[idx]) + __half2float(d0l[idx]);
            else         v = __half2float(d1h[idx]) + __half2float(d1l[idx]);
        }
        sh[i] = v;
    }
    __syncthreads();
    int p = tid >> 4, qq = tid & 15;
    float partial = 0.f;
    for (int kh = 0; kh < 3; kh++)
        for (int kw = 0; kw < 3; kw++) {
            int iw = p + kw - 1;
            if (iw < 0 || iw >= 16) continue;
            #pragma unroll
            for (int j = 0; j < 8; j++) {
                int ic = qq * 8 + j;
                partial += sh[(kh * 16 + iw) * 128 + ic] * wout[(kh * 3 + kw) * 128 + ic];
            }
        }
    ps[tid] = partial;
    __syncthreads();
    if (qq == 0) {
        float sum = bout[0];
        #pragma unroll
        for (int j = 0; j < 16; j++) sum += ps[p * 16 + j];
        out[((size_t)n * 16 + h) * 16 + p] = sum;
    }
}

extern "C" void kernel_launch(void* const* d_in, const int* in_sizes, int n_in,
                              void* d_out, int out_size) {
    const float* x    = (const float*)d_in[0];
    const float* wx0f = (const float*)d_in[1];
    const float* wh0f = (const float*)d_in[2];
    const float* b0f  = (const float*)d_in[3];
    const float* wx0b = (const float*)d_in[4];
    const float* wh0b = (const float*)d_in[5];
    const float* b0b  = (const float*)d_in[6];
    const float* wx1f = (const float*)d_in[7];
    const float* wh1f = (const float*)d_in[8];
    const float* b1f  = (const float*)d_in[9];
    const float* wx1b = (const float*)d_in[10];
    const float* wh1b = (const float*)d_in[11];
    const float* b1b  = (const float*)d_in[12];
    const float* wout = (const float*)d_in[13];
    const float* bout = (const float*)d_in[14];
    float* out = (float*)d_out;

    cudaFuncSetAttribute((const void*)conv_mma_kernel<1,2>, cudaFuncAttributeMaxDynamicSharedMemorySize, CSMEM);
    cudaFuncSetAttribute((const void*)conv_mma_kernel<2,4>, cudaFuncAttributeMaxDynamicSharedMemorySize, CSMEM);
    cudaFuncSetAttribute((const void*)lstm_persist_kernel, cudaFuncAttributeMaxDynamicSharedMemorySize, LSMEM);

    fp16 *wg, *xeh, *q0h, *q0l, *q1h, *q1l;
    cudaGetSymbolAddress((void**)&wg, g_w);
    cudaGetSymbolAddress((void**)&xeh, g_xeh);
    cudaGetSymbolAddress((void**)&q0h, g_q0h);
    cudaGetSymbolAddress((void**)&q0l, g_q0l);
    cudaGetSymbolAddress((void**)&q1h, g_q1h);
    cudaGetSymbolAddress((void**)&q1l, g_q1l);

    // cluster launch config for the LSTM (4 consecutive CTAs = one halo group)
    cudaLaunchConfig_t lcfg = {};
    lcfg.gridDim = dim3(128, 1, 1);
    lcfg.blockDim = dim3(512, 1, 1);
    lcfg.dynamicSmemBytes = LSMEM;
    lcfg.stream = 0;
    cudaLaunchAttribute lattr[1];
    lattr[0].id = cudaLaunchAttributeClusterDimension;
    lattr[0].val.clusterDim.x = 4;
    lattr[0].val.clusterDim.y = 1;
    lattr[0].val.clusterDim.z = 1;
    lcfg.attrs = lattr;
    lcfg.numAttrs = 1;

    wprep_all<<<(90*TAPSZ + 255)/256, 256>>>(wx0f, wx0b, wh0f, wh0b,
                                             wx1f, wx1b, wh1f, wh1b);          // 0
    embed_kernel<<<(NIMG*256*64 + 255)/256, 256>>>(x);                         // 1
    dim3 cgrid(NIMG, 2, 2);
    conv_mma_kernel<1,2><<<cgrid, 512, CSMEM>>>(xeh, xeh,
        wg + (size_t)0*TAPSZ, wg + (size_t)9*TAPSZ, b0f, b0b);                 // 2
    cudaLaunchKernelEx(&lcfg, lstm_persist_kernel,
        (const fp16*)(wg + (size_t)18*TAPSZ), (const fp16*)(wg + (size_t)27*TAPSZ),
        q0h, q0l, q1h, q1l);                                                   // 3 <- captured
    zero_states<<<2048, 256>>>();                                              // 4
    conv_mma_kernel<2,4><<<cgrid, 512, CSMEM>>>(q0h, q1h,
        wg + (size_t)36*TAPSZ, wg + (size_t)54*TAPSZ, b1f, b1b);               // 5
    cudaLaunchKernelEx(&lcfg, lstm_persist_kernel,
        (const fp16*)(wg + (size_t)72*TAPSZ), (const fp16*)(wg + (size_t)81*TAPSZ),
        q0h, q0l, q1h, q1l);                                                   // 6
    out_conv_kernel<<<NIMG*16, 256>>>(q0h, q0l, q1h, q1l, wout, bout, out);    // 7
}